// round 7
// baseline (speedup 1.0000x reference)
#include <cuda_runtime.h>
#include <cstdint>

// ---------------------------------------------------------------------------
// BiMambaLayer on GB300 — Round 5: R4 base + zero-cvt GEMM hot loop
// (all GEMM operands pre-rounded to TF32) + persistent global pointers.
// ---------------------------------------------------------------------------

namespace {
constexpr int kB   = 8;
constexpr int kL   = 4096;
constexpr int kDM  = 512;
constexpr int kDI  = 1024;
constexpr int kDXZ = 2048;
constexpr int kN   = 16;
constexpr int kR   = 32;
constexpr int kDBC = 64;
constexpr int kFF  = 2048;
constexpr int kT   = kB * kL;

// Offsets (floats) into the pre-rounded weight scratch g_wr
constexpr size_t oInF  = 0;                         // 2048*512
constexpr size_t oInB  = oInF  + 2048 * 512;
constexpr size_t oXpF  = oInB  + 2048 * 512;        // 64*1024
constexpr size_t oXpB  = oXpF  + 64 * 1024;
constexpr size_t oDtF  = oXpB  + 64 * 1024;         // 1024*32
constexpr size_t oDtB  = oDtF  + 1024 * 32;
constexpr size_t oOutF = oDtB  + 1024 * 32;         // 512*1024
constexpr size_t oOutB = oOutF + 512 * 1024;
constexpr size_t oF1   = oOutB + 512 * 1024;        // 2048*512
constexpr size_t oF2   = oF1   + 2048 * 512;        // 512*2048
constexpr size_t kWRTotal = oF2 + 512 * 2048;
}

__device__ float g_xz [(size_t)kT * kDXZ];
__device__ float g_xc [(size_t)kT * kDI];
__device__ float g_dbc[(size_t)kT * kDBC];
__device__ float g_dt [(size_t)kT * kDI];
__device__ float g_y  [(size_t)kT * kDI];
__device__ float g_mf [(size_t)kT * kDM];
__device__ float g_mb [(size_t)kT * kDM];
__device__ float g_h  [(size_t)kT * kDM];
__device__ float g_xr [(size_t)kT * kDM];    // tf32-rounded x
__device__ float g_wr [kWRTotal];            // tf32-rounded weights

__device__ __forceinline__ uint32_t f2tf32(float x) {
  uint32_t r;
  asm("cvt.rna.tf32.f32 %0, %1;" : "=r"(r) : "f"(x));
  return r;
}
__device__ __forceinline__ float roundtf(float x) {
  return __uint_as_float(f2tf32(x));
}

__device__ __forceinline__ void mma_tf32(float* d,
    uint32_t a0, uint32_t a1, uint32_t a2, uint32_t a3,
    uint32_t b0, uint32_t b1)
{
  asm volatile(
    "mma.sync.aligned.m16n8k8.row.col.f32.tf32.tf32.f32 "
    "{%0,%1,%2,%3}, {%4,%5,%6,%7}, {%8,%9}, {%0,%1,%2,%3};\n"
    : "+f"(d[0]), "+f"(d[1]), "+f"(d[2]), "+f"(d[3])
    : "r"(a0), "r"(a1), "r"(a2), "r"(a3), "r"(b0), "r"(b1));
}

// Vectorized tf32 rounding copy (n4 = element count / 4)
__global__ void round4_k(const float4* __restrict__ s, float4* __restrict__ d, int n4) {
  int i = blockIdx.x * blockDim.x + threadIdx.x;
  if (i < n4) {
    float4 v = s[i];
    v.x = roundtf(v.x); v.y = roundtf(v.y);
    v.z = roundtf(v.z); v.w = roundtf(v.w);
    d[i] = v;
  }
}

// ---------------------------------------------------------------------------
// C[M,N] = A[M,K](row stride lda) * W[N,K]^T (+ epilogue)
// A and W MUST already be tf32-rounded (no cvt in hot loop).
// EPI: 0 none, 1 softplus(+bias), 2 gelu(+bias), 3 +bias
// ROUND: 1 = round output to tf32 (when it feeds another GEMM's A).
// 128 threads = 4 warps (2x2), warp tile 64x32. smem [row][k], ST=36.
// Requires M%128==0, N%64==0, K%32==0.
// ---------------------------------------------------------------------------
template<int EPI, int ROUND>
__global__ void __launch_bounds__(128, 3) gemm_tc(
    const float* __restrict__ A, int lda,
    const float* __restrict__ W,
    const float* __restrict__ bias,
    float* __restrict__ C, int M, int N, int K)
{
  constexpr int BM = 128, BN = 64, BK = 32, ST = 36;
  __shared__ uint32_t As[BM * ST];
  __shared__ uint32_t Ws[BN * ST];

  const int tid  = threadIdx.x;
  const int lane = tid & 31;
  const int wid  = tid >> 5;
  const int wm   = (wid & 1) * 64;
  const int wn   = (wid >> 1) * 32;
  const size_t bm = (size_t)blockIdx.y * BM;
  const int bn   = blockIdx.x * BN;
  const int g4   = lane >> 2;
  const int t4   = lane & 3;

  float acc[4][4][4];
  #pragma unroll
  for (int i = 0; i < 4; i++)
    #pragma unroll
    for (int j = 0; j < 4; j++)
      #pragma unroll
      for (int c = 0; c < 4; c++) acc[i][j][c] = 0.f;

  const int ldR = tid >> 3;            // 0..15
  const int ldC = (tid & 7) << 2;      // 0,4,..,28

  // Persistent global pointers, advanced by BK floats per tile.
  const float4* aP[8];
  const float4* wP[4];
  #pragma unroll
  for (int i = 0; i < 8; i++)
    aP[i] = reinterpret_cast<const float4*>(&A[(bm + ldR + 16 * i) * (size_t)lda + ldC]);
  #pragma unroll
  for (int i = 0; i < 4; i++)
    wP[i] = reinterpret_cast<const float4*>(&W[(size_t)(bn + ldR + 16 * i) * K + ldC]);

  const int aStore = ldR * ST + ldC;   // + i*16*ST
  const int aBase  = (wm + g4) * ST + t4;
  const int bBase  = (wn + g4) * ST + t4;

  float4 aR[8], wR[4];

  // Prologue
  #pragma unroll
  for (int i = 0; i < 8; i++) { aR[i] = *aP[i]; aP[i] += BK / 4; }
  #pragma unroll
  for (int i = 0; i < 4; i++) { wR[i] = *wP[i]; wP[i] += BK / 4; }
  #pragma unroll
  for (int i = 0; i < 8; i++)
    *reinterpret_cast<float4*>(reinterpret_cast<float*>(&As[aStore + i * 16 * ST])) = aR[i];
  #pragma unroll
  for (int i = 0; i < 4; i++)
    *reinterpret_cast<float4*>(reinterpret_cast<float*>(&Ws[aStore + i * 16 * ST])) = wR[i];
  __syncthreads();

  for (int k0 = 0; k0 < K; k0 += BK) {
    const bool more = (k0 + BK) < K;
    if (more) {
      #pragma unroll
      for (int i = 0; i < 8; i++) { aR[i] = *aP[i]; aP[i] += BK / 4; }
      #pragma unroll
      for (int i = 0; i < 4; i++) { wR[i] = *wP[i]; wP[i] += BK / 4; }
    }

    #pragma unroll
    for (int kk = 0; kk < 4; kk++) {
      uint32_t a[4][4];
      uint32_t b[4][2];
      #pragma unroll
      for (int mi = 0; mi < 4; mi++) {
        const int o = aBase + mi * (16 * ST) + kk * 8;
        a[mi][0] = As[o];
        a[mi][1] = As[o + 8 * ST];
        a[mi][2] = As[o + 4];
        a[mi][3] = As[o + 8 * ST + 4];
      }
      #pragma unroll
      for (int nj = 0; nj < 4; nj++) {
        const int o = bBase + nj * (8 * ST) + kk * 8;
        b[nj][0] = Ws[o];
        b[nj][1] = Ws[o + 4];
      }
      #pragma unroll
      for (int mi = 0; mi < 4; mi++)
        #pragma unroll
        for (int nj = 0; nj < 4; nj++)
          mma_tf32(acc[mi][nj], a[mi][0], a[mi][1], a[mi][2], a[mi][3],
                   b[nj][0], b[nj][1]);
    }
    __syncthreads();
    if (more) {
      #pragma unroll
      for (int i = 0; i < 8; i++)
        *reinterpret_cast<float4*>(reinterpret_cast<float*>(&As[aStore + i * 16 * ST])) = aR[i];
      #pragma unroll
      for (int i = 0; i < 4; i++)
        *reinterpret_cast<float4*>(reinterpret_cast<float*>(&Ws[aStore + i * 16 * ST])) = wR[i];
      __syncthreads();
    }
  }

  // Epilogue
  #pragma unroll
  for (int mi = 0; mi < 4; mi++) {
    #pragma unroll
    for (int nj = 0; nj < 4; nj++) {
      size_t r0 = bm + wm + mi * 16 + g4;
      int c0 = bn + wn + nj * 8 + 2 * t4;
      #pragma unroll
      for (int half = 0; half < 2; half++) {
        size_t row = r0 + half * 8;
        float2 v;
        v.x = acc[mi][nj][half * 2 + 0];
        v.y = acc[mi][nj][half * 2 + 1];
        if (EPI == 1) {
          v.x += __ldg(&bias[c0]);     v.y += __ldg(&bias[c0 + 1]);
          v.x = fmaxf(v.x, 0.f) + log1pf(__expf(-fabsf(v.x)));
          v.y = fmaxf(v.y, 0.f) + log1pf(__expf(-fabsf(v.y)));
        } else if (EPI == 2) {
          v.x += __ldg(&bias[c0]);     v.y += __ldg(&bias[c0 + 1]);
          float tx = tanhf(0.7978845608028654f * (v.x + 0.044715f * v.x * v.x * v.x));
          float ty = tanhf(0.7978845608028654f * (v.y + 0.044715f * v.y * v.y * v.y));
          v.x = 0.5f * v.x * (1.f + tx);
          v.y = 0.5f * v.y * (1.f + ty);
        } else if (EPI == 3) {
          v.x += __ldg(&bias[c0]);     v.y += __ldg(&bias[c0 + 1]);
        }
        if (ROUND) { v.x = roundtf(v.x); v.y = roundtf(v.y); }
        *reinterpret_cast<float2*>(&C[row * N + c0]) = v;
      }
    }
  }
}

// ---------------------------------------------------------------------------
// Depthwise causal conv (k=4) + bias + silu; output tf32-rounded (feeds GEMM).
// ---------------------------------------------------------------------------
__global__ void conv_silu_k(const float* __restrict__ cw,
                            const float* __restrict__ cb, int dir)
{
  int i = blockIdx.x * blockDim.x + threadIdx.x;
  int d = i & (kDI - 1);
  int tok = i >> 10;
  int pos = tok & (kL - 1);
  float acc = __ldg(&cb[d]);
  #pragma unroll
  for (int j = 0; j < 4; j++) {
    int o = (dir > 0) ? (j - 3) : (3 - j);
    int p = pos + o;
    if (p >= 0 && p < kL)
      acc = fmaf(__ldg(&cw[d * 4 + j]), g_xz[(size_t)(tok + o) * kDXZ + d], acc);
  }
  g_xc[i] = roundtf(acc / (1.f + __expf(-acc)));
}

// ---------------------------------------------------------------------------
// Selective scan, warp = 2 channels (16 state lanes each); y tf32-rounded.
// ---------------------------------------------------------------------------
__global__ void scan_k(const float* __restrict__ A_log,
                       const float* __restrict__ Dp, int dir)
{
  int gw   = (blockIdx.x * blockDim.x + threadIdx.x) >> 5;
  int lane = threadIdx.x & 31;
  int half = lane >> 4;
  int n    = lane & 15;
  int ch   = gw * 2 + half;
  int b    = ch >> 10;
  int d    = ch & (kDI - 1);

  float A  = -__expf(__ldg(&A_log[d * kN + n]));
  float Dv = __ldg(&Dp[d]);
  float h  = 0.f;
  const size_t tokbase = (size_t)b * kL;

  for (int u = 0; u < kL; ++u) {
    int pos = (dir > 0) ? u : (kL - 1 - u);
    size_t tok = tokbase + pos;
    float dtv = g_dt [tok * kDI  + d];
    float xv  = g_xc [tok * kDI  + d];
    float Bv  = g_dbc[tok * kDBC + kR + n];
    float Cv  = g_dbc[tok * kDBC + kR + kN + n];
    float a   = __expf(dtv * A);
    h = fmaf(a, h, dtv * xv * Bv);
    float p = h * Cv;
    p += __shfl_xor_sync(0xffffffffu, p, 1);
    p += __shfl_xor_sync(0xffffffffu, p, 2);
    p += __shfl_xor_sync(0xffffffffu, p, 4);
    p += __shfl_xor_sync(0xffffffffu, p, 8);
    if (n == 0) {
      float zv = g_xz[tok * kDXZ + kDI + d];
      float sz = zv / (1.f + __expf(-zv));
      g_y[tok * kDI + d] = roundtf((p + xv * Dv) * sz);
    }
  }
}

// ---------------------------------------------------------------------------
// LayerNorms
// ---------------------------------------------------------------------------
__device__ __forceinline__ float warp_sum(float v) {
  v += __shfl_xor_sync(0xffffffffu, v, 16);
  v += __shfl_xor_sync(0xffffffffu, v, 8);
  v += __shfl_xor_sync(0xffffffffu, v, 4);
  v += __shfl_xor_sync(0xffffffffu, v, 2);
  v += __shfl_xor_sync(0xffffffffu, v, 1);
  return v;
}

// h = 0.5*(LN(x+mf)+LN(x+mb)), stored tf32-rounded (feeds ffn1 GEMM).
__global__ void ln_combine_k(const float* __restrict__ x,
    const float* __restrict__ gf, const float* __restrict__ bf,
    const float* __restrict__ gb, const float* __restrict__ bb)
{
  int row  = blockIdx.x * (blockDim.x >> 5) + (threadIdx.x >> 5);
  int lane = threadIdx.x & 31;
  const float* xr = x    + (size_t)row * kDM;
  const float* fr = g_mf + (size_t)row * kDM;
  const float* br = g_mb + (size_t)row * kDM;

  float u[16], v[16];
  float su = 0.f, sv = 0.f;
  #pragma unroll
  for (int k = 0; k < 4; k++) {
    int idx = (k * 32 + lane) * 4;
    float4 a  = *reinterpret_cast<const float4*>(xr + idx);
    float4 m1 = *reinterpret_cast<const float4*>(fr + idx);
    float4 m2 = *reinterpret_cast<const float4*>(br + idx);
    u[k*4+0]=a.x+m1.x; u[k*4+1]=a.y+m1.y; u[k*4+2]=a.z+m1.z; u[k*4+3]=a.w+m1.w;
    v[k*4+0]=a.x+m2.x; v[k*4+1]=a.y+m2.y; v[k*4+2]=a.z+m2.z; v[k*4+3]=a.w+m2.w;
    #pragma unroll
    for (int c = 0; c < 4; c++) { su += u[k*4+c]; sv += v[k*4+c]; }
  }
  float muU = warp_sum(su) * (1.f / kDM);
  float muV = warp_sum(sv) * (1.f / kDM);
  float qu = 0.f, qv = 0.f;
  #pragma unroll
  for (int c = 0; c < 16; c++) {
    float du = u[c] - muU, dv = v[c] - muV;
    qu += du * du; qv += dv * dv;
  }
  float rsU = rsqrtf(warp_sum(qu) * (1.f / kDM) + 1e-5f);
  float rsV = rsqrtf(warp_sum(qv) * (1.f / kDM) + 1e-5f);

  float* hr = g_h + (size_t)row * kDM;
  #pragma unroll
  for (int k = 0; k < 4; k++) {
    int idx = (k * 32 + lane) * 4;
    float4 o;
    #pragma unroll
    for (int c = 0; c < 4; c++) {
      int f = idx + c;
      float a = (u[k*4+c] - muU) * rsU * __ldg(&gf[f]) + __ldg(&bf[f]);
      float bvv = (v[k*4+c] - muV) * rsV * __ldg(&gb[f]) + __ldg(&bb[f]);
      ((float*)&o)[c] = roundtf(0.5f * (a + bvv));
    }
    *reinterpret_cast<float4*>(hr + idx) = o;
  }
}

__global__ void ln_final_k(const float* __restrict__ ff,
    const float* __restrict__ g, const float* __restrict__ bia,
    float* __restrict__ out)
{
  int row  = blockIdx.x * (blockDim.x >> 5) + (threadIdx.x >> 5);
  int lane = threadIdx.x & 31;
  const float* hr = g_h + (size_t)row * kDM;
  const float* fr = ff  + (size_t)row * kDM;

  float u[16];
  float su = 0.f;
  #pragma unroll
  for (int k = 0; k < 4; k++) {
    int idx = (k * 32 + lane) * 4;
    float4 a  = *reinterpret_cast<const float4*>(hr + idx);
    float4 m1 = *reinterpret_cast<const float4*>(fr + idx);
    u[k*4+0]=a.x+m1.x; u[k*4+1]=a.y+m1.y; u[k*4+2]=a.z+m1.z; u[k*4+3]=a.w+m1.w;
    #pragma unroll
    for (int c = 0; c < 4; c++) su += u[k*4+c];
  }
  float mu = warp_sum(su) * (1.f / kDM);
  float q = 0.f;
  #pragma unroll
  for (int c = 0; c < 16; c++) { float d = u[c] - mu; q += d * d; }
  float rs = rsqrtf(warp_sum(q) * (1.f / kDM) + 1e-5f);

  float* orow = out + (size_t)row * kDM;
  #pragma unroll
  for (int k = 0; k < 4; k++) {
    int idx = (k * 32 + lane) * 4;
    float4 o;
    #pragma unroll
    for (int c = 0; c < 4; c++) {
      int f = idx + c;
      ((float*)&o)[c] = (u[k*4+c] - mu) * rs * __ldg(&g[f]) + __ldg(&bia[f]);
    }
    *reinterpret_cast<float4*>(orow + idx) = o;
  }
}

// ---------------------------------------------------------------------------
// Launch
// ---------------------------------------------------------------------------
extern "C" void kernel_launch(void* const* d_in, const int* in_sizes, int n_in,
                              void* d_out, int out_size)
{
  const float* x = (const float*)d_in[0];
  const float* const* Pf = (const float* const*)&d_in[1];
  const float* const* Pb = (const float* const*)&d_in[10];
  const float* ln_f_g  = (const float*)d_in[19];
  const float* ln_f_b  = (const float*)d_in[20];
  const float* ln_b_g  = (const float*)d_in[21];
  const float* ln_b_b  = (const float*)d_in[22];
  const float* ln_ff_g = (const float*)d_in[23];
  const float* ln_ff_b = (const float*)d_in[24];
  const float* ffn_w1  = (const float*)d_in[25];
  const float* ffn_b1  = (const float*)d_in[26];
  const float* ffn_w2  = (const float*)d_in[27];
  const float* ffn_b2  = (const float*)d_in[28];
  float* out = (float*)d_out;

  void *p_xz, *p_xc, *p_dbc, *p_dt, *p_y, *p_mf, *p_mb, *p_h, *p_xr, *p_wr;
  cudaGetSymbolAddress(&p_xz,  g_xz);
  cudaGetSymbolAddress(&p_xc,  g_xc);
  cudaGetSymbolAddress(&p_dbc, g_dbc);
  cudaGetSymbolAddress(&p_dt,  g_dt);
  cudaGetSymbolAddress(&p_y,   g_y);
  cudaGetSymbolAddress(&p_mf,  g_mf);
  cudaGetSymbolAddress(&p_mb,  g_mb);
  cudaGetSymbolAddress(&p_h,   g_h);
  cudaGetSymbolAddress(&p_xr,  g_xr);
  cudaGetSymbolAddress(&p_wr,  g_wr);
  float* xr = (float*)p_xr;
  float* wr = (float*)p_wr;

  const dim3 blk(128);
  const int rowsY = kT / 128;   // 256

  // --- Pre-round x and all weights to TF32 (removes cvt from GEMM hot loop) ---
  auto rnd = [&](const float* src, float* dst, size_t n) {
    int n4 = (int)(n / 4);
    round4_k<<<(n4 + 255) / 256, dim3(256)>>>(
        (const float4*)src, (float4*)dst, n4);
  };
  rnd(x, xr, (size_t)kT * kDM);
  rnd(Pf[0], wr + oInF,  2048 * 512);
  rnd(Pb[0], wr + oInB,  2048 * 512);
  rnd(Pf[3], wr + oXpF,  64 * 1024);
  rnd(Pb[3], wr + oXpB,  64 * 1024);
  rnd(Pf[4], wr + oDtF,  1024 * 32);
  rnd(Pb[4], wr + oDtB,  1024 * 32);
  rnd(Pf[8], wr + oOutF, 512 * 1024);
  rnd(Pb[8], wr + oOutB, 512 * 1024);
  rnd(ffn_w1, wr + oF1,  2048 * 512);
  rnd(ffn_w2, wr + oF2,  512 * 2048);

  auto run_block = [&](const float* const* P, float* mout, int dir,
                       const float* w_in, const float* w_xp,
                       const float* w_dt, const float* w_out) {
    gemm_tc<0,0><<<dim3(kDXZ / 64, rowsY), blk>>>(xr, kDM, w_in, nullptr,
                                                  (float*)p_xz, kT, kDXZ, kDM);
    conv_silu_k<<<(kT * kDI) / 256, dim3(256)>>>(P[1], P[2], dir);
    gemm_tc<0,1><<<dim3(kDBC / 64, rowsY), blk>>>((const float*)p_xc, kDI, w_xp,
                                                  nullptr, (float*)p_dbc, kT, kDBC, kDI);
    gemm_tc<1,0><<<dim3(kDI / 64, rowsY), blk>>>((const float*)p_dbc, kDBC, w_dt,
                                                 P[5], (float*)p_dt, kT, kDI, kR);
    scan_k<<<512, dim3(256)>>>(P[6], P[7], dir);
    gemm_tc<0,0><<<dim3(kDM / 64, rowsY), blk>>>((const float*)p_y, kDI, w_out,
                                                 nullptr, mout, kT, kDM, kDI);
  };

  run_block(Pf, (float*)p_mf, +1, wr + oInF, wr + oXpF, wr + oDtF, wr + oOutF);
  run_block(Pb, (float*)p_mb, -1, wr + oInB, wr + oXpB, wr + oDtB, wr + oOutB);

  ln_combine_k<<<kT / 8, dim3(256)>>>(x, ln_f_g, ln_f_b, ln_b_g, ln_b_b);

  gemm_tc<2,1><<<dim3(kFF / 64, rowsY), blk>>>((const float*)p_h, kDM, wr + oF1,
                                               ffn_b1, (float*)p_xz, kT, kFF, kDM);
  gemm_tc<3,0><<<dim3(kDM / 64, rowsY), blk>>>((const float*)p_xz, kFF, wr + oF2,
                                               ffn_b2, (float*)p_mf, kT, kDM, kFF);

  ln_final_k<<<kT / 8, dim3(256)>>>((const float*)p_mf, ln_ff_g, ln_ff_b, out);
}

// round 8
// speedup vs baseline: 1.0039x; 1.0039x over previous
#include <cuda_runtime.h>
#include <cstdint>

// ---------------------------------------------------------------------------
// BiMambaLayer on GB300 — Round 6: R4/R5 base + cp.async 2-stage pipelined
// TF32 GEMM (pre-rounded operands, BK=16, ST=20, 128 thr, 4 CTA/SM target).
// ---------------------------------------------------------------------------

namespace {
constexpr int kB   = 8;
constexpr int kL   = 4096;
constexpr int kDM  = 512;
constexpr int kDI  = 1024;
constexpr int kDXZ = 2048;
constexpr int kN   = 16;
constexpr int kR   = 32;
constexpr int kDBC = 64;
constexpr int kFF  = 2048;
constexpr int kT   = kB * kL;

constexpr size_t oInF  = 0;
constexpr size_t oInB  = oInF  + 2048 * 512;
constexpr size_t oXpF  = oInB  + 2048 * 512;
constexpr size_t oXpB  = oXpF  + 64 * 1024;
constexpr size_t oDtF  = oXpB  + 64 * 1024;
constexpr size_t oDtB  = oDtF  + 1024 * 32;
constexpr size_t oOutF = oDtB  + 1024 * 32;
constexpr size_t oOutB = oOutF + 512 * 1024;
constexpr size_t oF1   = oOutB + 512 * 1024;
constexpr size_t oF2   = oF1   + 2048 * 512;
constexpr size_t kWRTotal = oF2 + 512 * 2048;
}

__device__ float g_xz [(size_t)kT * kDXZ];
__device__ float g_xc [(size_t)kT * kDI];
__device__ float g_dbc[(size_t)kT * kDBC];
__device__ float g_dt [(size_t)kT * kDI];
__device__ float g_y  [(size_t)kT * kDI];
__device__ float g_mf [(size_t)kT * kDM];
__device__ float g_mb [(size_t)kT * kDM];
__device__ float g_h  [(size_t)kT * kDM];
__device__ float g_xr [(size_t)kT * kDM];
__device__ float g_wr [kWRTotal];

__device__ __forceinline__ uint32_t f2tf32(float x) {
  uint32_t r;
  asm("cvt.rna.tf32.f32 %0, %1;" : "=r"(r) : "f"(x));
  return r;
}
__device__ __forceinline__ float roundtf(float x) {
  return __uint_as_float(f2tf32(x));
}

__device__ __forceinline__ void mma_tf32(float* d,
    uint32_t a0, uint32_t a1, uint32_t a2, uint32_t a3,
    uint32_t b0, uint32_t b1)
{
  asm volatile(
    "mma.sync.aligned.m16n8k8.row.col.f32.tf32.tf32.f32 "
    "{%0,%1,%2,%3}, {%4,%5,%6,%7}, {%8,%9}, {%0,%1,%2,%3};\n"
    : "+f"(d[0]), "+f"(d[1]), "+f"(d[2]), "+f"(d[3])
    : "r"(a0), "r"(a1), "r"(a2), "r"(a3), "r"(b0), "r"(b1));
}

__device__ __forceinline__ void cpa16(uint32_t s, const float* g) {
  asm volatile("cp.async.cg.shared.global [%0], [%1], 16;" :: "r"(s), "l"(g));
}
__device__ __forceinline__ void cpa_commit() {
  asm volatile("cp.async.commit_group;" ::: "memory");
}
template<int NN>
__device__ __forceinline__ void cpa_wait() {
  asm volatile("cp.async.wait_group %0;" :: "n"(NN) : "memory");
}

__global__ void round4_k(const float4* __restrict__ s, float4* __restrict__ d, int n4) {
  int i = blockIdx.x * blockDim.x + threadIdx.x;
  if (i < n4) {
    float4 v = s[i];
    v.x = roundtf(v.x); v.y = roundtf(v.y);
    v.z = roundtf(v.z); v.w = roundtf(v.w);
    d[i] = v;
  }
}

// ---------------------------------------------------------------------------
// C[M,N] = A[M,K](row stride lda) * W[N,K]^T (+ epilogue)
// A, W pre-rounded to TF32. cp.async double-buffered, BK=16, ST=20.
// EPI: 0 none, 1 softplus(+bias), 2 gelu(+bias), 3 +bias. ROUND: tf32 output.
// 128 threads = 4 warps (2x2), warp tile 64x32. M%128==0, N%64==0, K%16==0.
// ---------------------------------------------------------------------------
template<int EPI, int ROUND>
__global__ void __launch_bounds__(128, 4) gemm_tc(
    const float* __restrict__ A, int lda,
    const float* __restrict__ W,
    const float* __restrict__ bias,
    float* __restrict__ C, int M, int N, int K)
{
  constexpr int BM = 128, BN = 64, BK = 16, ST = 20;
  constexpr int STAGE  = (BM + BN) * ST;      // words per stage
  constexpr int STAGEB = STAGE * 4;           // bytes per stage
  __shared__ uint32_t Sm[2 * STAGE];

  const int tid  = threadIdx.x;
  const int lane = tid & 31;
  const int wid  = tid >> 5;
  const int wm   = (wid & 1) * 64;
  const int wn   = (wid >> 1) * 32;
  const size_t bm = (size_t)blockIdx.y * BM;
  const int bn   = blockIdx.x * BN;
  const int g4   = lane >> 2;
  const int t4   = lane & 3;

  float acc[4][4][4];
  #pragma unroll
  for (int i = 0; i < 4; i++)
    #pragma unroll
    for (int j = 0; j < 4; j++)
      #pragma unroll
      for (int c = 0; c < 4; c++) acc[i][j][c] = 0.f;

  // Copy geometry: A 128x16 = 512 float4 (4/thread), W 64x16 = 256 (2/thread)
  const int rA = tid >> 2;                 // base row 0..31 step 32
  const int c4 = (tid & 3) << 2;           // k col {0,4,8,12}

  const float* aG[4];
  const float* wG[2];
  uint32_t aDst[4], wDst[2];
  const uint32_t smemBase = (uint32_t)__cvta_generic_to_shared(Sm);
  #pragma unroll
  for (int i = 0; i < 4; i++) {
    int r = rA + 32 * i;
    aG[i]   = &A[(bm + r) * (size_t)lda + c4];
    aDst[i] = smemBase + (uint32_t)(r * ST + c4) * 4u;
  }
  #pragma unroll
  for (int i = 0; i < 2; i++) {
    int r = rA + 32 * i;
    wG[i]   = &W[(size_t)(bn + r) * K + c4];
    wDst[i] = smemBase + (uint32_t)(BM * ST + r * ST + c4) * 4u;
  }

  auto issue = [&](int st) {
    const uint32_t so = (uint32_t)st * STAGEB;
    #pragma unroll
    for (int i = 0; i < 4; i++) { cpa16(aDst[i] + so, aG[i]); aG[i] += BK; }
    #pragma unroll
    for (int i = 0; i < 2; i++) { cpa16(wDst[i] + so, wG[i]); wG[i] += BK; }
    cpa_commit();
  };

  const int aBase = (wm + g4) * ST + t4;
  const int bBase = BM * ST + (wn + g4) * ST + t4;

  issue(0);

  int cur = 0;
  for (int k0 = 0; k0 < K; k0 += BK) {
    if (k0 + BK < K) { issue(cur ^ 1); cpa_wait<1>(); }
    else             { cpa_wait<0>(); }
    __syncthreads();

    const uint32_t* as = Sm + cur * STAGE;
    #pragma unroll
    for (int kk = 0; kk < 2; kk++) {
      uint32_t a[4][4];
      uint32_t b[4][2];
      #pragma unroll
      for (int mi = 0; mi < 4; mi++) {
        const int o = aBase + mi * (16 * ST) + kk * 8;
        a[mi][0] = as[o];
        a[mi][1] = as[o + 8 * ST];
        a[mi][2] = as[o + 4];
        a[mi][3] = as[o + 8 * ST + 4];
      }
      #pragma unroll
      for (int nj = 0; nj < 4; nj++) {
        const int o = bBase + nj * (8 * ST) + kk * 8;
        b[nj][0] = as[o];
        b[nj][1] = as[o + 4];
      }
      #pragma unroll
      for (int mi = 0; mi < 4; mi++)
        #pragma unroll
        for (int nj = 0; nj < 4; nj++)
          mma_tf32(acc[mi][nj], a[mi][0], a[mi][1], a[mi][2], a[mi][3],
                   b[nj][0], b[nj][1]);
    }
    __syncthreads();
    cur ^= 1;
  }

  // Epilogue
  #pragma unroll
  for (int mi = 0; mi < 4; mi++) {
    #pragma unroll
    for (int nj = 0; nj < 4; nj++) {
      size_t r0 = bm + wm + mi * 16 + g4;
      int c0 = bn + wn + nj * 8 + 2 * t4;
      #pragma unroll
      for (int half = 0; half < 2; half++) {
        size_t row = r0 + half * 8;
        float2 v;
        v.x = acc[mi][nj][half * 2 + 0];
        v.y = acc[mi][nj][half * 2 + 1];
        if (EPI == 1) {
          v.x += __ldg(&bias[c0]);     v.y += __ldg(&bias[c0 + 1]);
          v.x = fmaxf(v.x, 0.f) + log1pf(__expf(-fabsf(v.x)));
          v.y = fmaxf(v.y, 0.f) + log1pf(__expf(-fabsf(v.y)));
        } else if (EPI == 2) {
          v.x += __ldg(&bias[c0]);     v.y += __ldg(&bias[c0 + 1]);
          float tx = tanhf(0.7978845608028654f * (v.x + 0.044715f * v.x * v.x * v.x));
          float ty = tanhf(0.7978845608028654f * (v.y + 0.044715f * v.y * v.y * v.y));
          v.x = 0.5f * v.x * (1.f + tx);
          v.y = 0.5f * v.y * (1.f + ty);
        } else if (EPI == 3) {
          v.x += __ldg(&bias[c0]);     v.y += __ldg(&bias[c0 + 1]);
        }
        if (ROUND) { v.x = roundtf(v.x); v.y = roundtf(v.y); }
        *reinterpret_cast<float2*>(&C[row * N + c0]) = v;
      }
    }
  }
}

// ---------------------------------------------------------------------------
// Depthwise causal conv (k=4) + bias + silu; output tf32-rounded.
// ---------------------------------------------------------------------------
__global__ void conv_silu_k(const float* __restrict__ cw,
                            const float* __restrict__ cb, int dir)
{
  int i = blockIdx.x * blockDim.x + threadIdx.x;
  int d = i & (kDI - 1);
  int tok = i >> 10;
  int pos = tok & (kL - 1);
  float acc = __ldg(&cb[d]);
  #pragma unroll
  for (int j = 0; j < 4; j++) {
    int o = (dir > 0) ? (j - 3) : (3 - j);
    int p = pos + o;
    if (p >= 0 && p < kL)
      acc = fmaf(__ldg(&cw[d * 4 + j]), g_xz[(size_t)(tok + o) * kDXZ + d], acc);
  }
  g_xc[i] = roundtf(acc / (1.f + __expf(-acc)));
}

// ---------------------------------------------------------------------------
// Selective scan; y tf32-rounded.
// ---------------------------------------------------------------------------
__global__ void scan_k(const float* __restrict__ A_log,
                       const float* __restrict__ Dp, int dir)
{
  int gw   = (blockIdx.x * blockDim.x + threadIdx.x) >> 5;
  int lane = threadIdx.x & 31;
  int half = lane >> 4;
  int n    = lane & 15;
  int ch   = gw * 2 + half;
  int b    = ch >> 10;
  int d    = ch & (kDI - 1);

  float A  = -__expf(__ldg(&A_log[d * kN + n]));
  float Dv = __ldg(&Dp[d]);
  float h  = 0.f;
  const size_t tokbase = (size_t)b * kL;

  for (int u = 0; u < kL; ++u) {
    int pos = (dir > 0) ? u : (kL - 1 - u);
    size_t tok = tokbase + pos;
    float dtv = g_dt [tok * kDI  + d];
    float xv  = g_xc [tok * kDI  + d];
    float Bv  = g_dbc[tok * kDBC + kR + n];
    float Cv  = g_dbc[tok * kDBC + kR + kN + n];
    float a   = __expf(dtv * A);
    h = fmaf(a, h, dtv * xv * Bv);
    float p = h * Cv;
    p += __shfl_xor_sync(0xffffffffu, p, 1);
    p += __shfl_xor_sync(0xffffffffu, p, 2);
    p += __shfl_xor_sync(0xffffffffu, p, 4);
    p += __shfl_xor_sync(0xffffffffu, p, 8);
    if (n == 0) {
      float zv = g_xz[tok * kDXZ + kDI + d];
      float sz = zv / (1.f + __expf(-zv));
      g_y[tok * kDI + d] = roundtf((p + xv * Dv) * sz);
    }
  }
}

// ---------------------------------------------------------------------------
// LayerNorms
// ---------------------------------------------------------------------------
__device__ __forceinline__ float warp_sum(float v) {
  v += __shfl_xor_sync(0xffffffffu, v, 16);
  v += __shfl_xor_sync(0xffffffffu, v, 8);
  v += __shfl_xor_sync(0xffffffffu, v, 4);
  v += __shfl_xor_sync(0xffffffffu, v, 2);
  v += __shfl_xor_sync(0xffffffffu, v, 1);
  return v;
}

__global__ void ln_combine_k(const float* __restrict__ x,
    const float* __restrict__ gf, const float* __restrict__ bf,
    const float* __restrict__ gb, const float* __restrict__ bb)
{
  int row  = blockIdx.x * (blockDim.x >> 5) + (threadIdx.x >> 5);
  int lane = threadIdx.x & 31;
  const float* xr = x    + (size_t)row * kDM;
  const float* fr = g_mf + (size_t)row * kDM;
  const float* br = g_mb + (size_t)row * kDM;

  float u[16], v[16];
  float su = 0.f, sv = 0.f;
  #pragma unroll
  for (int k = 0; k < 4; k++) {
    int idx = (k * 32 + lane) * 4;
    float4 a  = *reinterpret_cast<const float4*>(xr + idx);
    float4 m1 = *reinterpret_cast<const float4*>(fr + idx);
    float4 m2 = *reinterpret_cast<const float4*>(br + idx);
    u[k*4+0]=a.x+m1.x; u[k*4+1]=a.y+m1.y; u[k*4+2]=a.z+m1.z; u[k*4+3]=a.w+m1.w;
    v[k*4+0]=a.x+m2.x; v[k*4+1]=a.y+m2.y; v[k*4+2]=a.z+m2.z; v[k*4+3]=a.w+m2.w;
    #pragma unroll
    for (int c = 0; c < 4; c++) { su += u[k*4+c]; sv += v[k*4+c]; }
  }
  float muU = warp_sum(su) * (1.f / kDM);
  float muV = warp_sum(sv) * (1.f / kDM);
  float qu = 0.f, qv = 0.f;
  #pragma unroll
  for (int c = 0; c < 16; c++) {
    float du = u[c] - muU, dv = v[c] - muV;
    qu += du * du; qv += dv * dv;
  }
  float rsU = rsqrtf(warp_sum(qu) * (1.f / kDM) + 1e-5f);
  float rsV = rsqrtf(warp_sum(qv) * (1.f / kDM) + 1e-5f);

  float* hr = g_h + (size_t)row * kDM;
  #pragma unroll
  for (int k = 0; k < 4; k++) {
    int idx = (k * 32 + lane) * 4;
    float4 o;
    #pragma unroll
    for (int c = 0; c < 4; c++) {
      int f = idx + c;
      float a = (u[k*4+c] - muU) * rsU * __ldg(&gf[f]) + __ldg(&bf[f]);
      float bvv = (v[k*4+c] - muV) * rsV * __ldg(&gb[f]) + __ldg(&bb[f]);
      ((float*)&o)[c] = roundtf(0.5f * (a + bvv));
    }
    *reinterpret_cast<float4*>(hr + idx) = o;
  }
}

__global__ void ln_final_k(const float* __restrict__ ff,
    const float* __restrict__ g, const float* __restrict__ bia,
    float* __restrict__ out)
{
  int row  = blockIdx.x * (blockDim.x >> 5) + (threadIdx.x >> 5);
  int lane = threadIdx.x & 31;
  const float* hr = g_h + (size_t)row * kDM;
  const float* fr = ff  + (size_t)row * kDM;

  float u[16];
  float su = 0.f;
  #pragma unroll
  for (int k = 0; k < 4; k++) {
    int idx = (k * 32 + lane) * 4;
    float4 a  = *reinterpret_cast<const float4*>(hr + idx);
    float4 m1 = *reinterpret_cast<const float4*>(fr + idx);
    u[k*4+0]=a.x+m1.x; u[k*4+1]=a.y+m1.y; u[k*4+2]=a.z+m1.z; u[k*4+3]=a.w+m1.w;
    #pragma unroll
    for (int c = 0; c < 4; c++) su += u[k*4+c];
  }
  float mu = warp_sum(su) * (1.f / kDM);
  float q = 0.f;
  #pragma unroll
  for (int c = 0; c < 16; c++) { float d = u[c] - mu; q += d * d; }
  float rs = rsqrtf(warp_sum(q) * (1.f / kDM) + 1e-5f);

  float* orow = out + (size_t)row * kDM;
  #pragma unroll
  for (int k = 0; k < 4; k++) {
    int idx = (k * 32 + lane) * 4;
    float4 o;
    #pragma unroll
    for (int c = 0; c < 4; c++) {
      int f = idx + c;
      ((float*)&o)[c] = (u[k*4+c] - mu) * rs * __ldg(&g[f]) + __ldg(&bia[f]);
    }
    *reinterpret_cast<float4*>(orow + idx) = o;
  }
}

// ---------------------------------------------------------------------------
// Launch
// ---------------------------------------------------------------------------
extern "C" void kernel_launch(void* const* d_in, const int* in_sizes, int n_in,
                              void* d_out, int out_size)
{
  const float* x = (const float*)d_in[0];
  const float* const* Pf = (const float* const*)&d_in[1];
  const float* const* Pb = (const float* const*)&d_in[10];
  const float* ln_f_g  = (const float*)d_in[19];
  const float* ln_f_b  = (const float*)d_in[20];
  const float* ln_b_g  = (const float*)d_in[21];
  const float* ln_b_b  = (const float*)d_in[22];
  const float* ln_ff_g = (const float*)d_in[23];
  const float* ln_ff_b = (const float*)d_in[24];
  const float* ffn_w1  = (const float*)d_in[25];
  const float* ffn_b1  = (const float*)d_in[26];
  const float* ffn_w2  = (const float*)d_in[27];
  const float* ffn_b2  = (const float*)d_in[28];
  float* out = (float*)d_out;

  void *p_xz, *p_xc, *p_dbc, *p_dt, *p_y, *p_mf, *p_mb, *p_h, *p_xr, *p_wr;
  cudaGetSymbolAddress(&p_xz,  g_xz);
  cudaGetSymbolAddress(&p_xc,  g_xc);
  cudaGetSymbolAddress(&p_dbc, g_dbc);
  cudaGetSymbolAddress(&p_dt,  g_dt);
  cudaGetSymbolAddress(&p_y,   g_y);
  cudaGetSymbolAddress(&p_mf,  g_mf);
  cudaGetSymbolAddress(&p_mb,  g_mb);
  cudaGetSymbolAddress(&p_h,   g_h);
  cudaGetSymbolAddress(&p_xr,  g_xr);
  cudaGetSymbolAddress(&p_wr,  g_wr);
  float* xr = (float*)p_xr;
  float* wr = (float*)p_wr;

  const dim3 blk(128);
  const int rowsY = kT / 128;   // 256

  auto rnd = [&](const float* src, float* dst, size_t n) {
    int n4 = (int)(n / 4);
    round4_k<<<(n4 + 255) / 256, dim3(256)>>>(
        (const float4*)src, (float4*)dst, n4);
  };
  rnd(x, xr, (size_t)kT * kDM);
  rnd(Pf[0], wr + oInF,  2048 * 512);
  rnd(Pb[0], wr + oInB,  2048 * 512);
  rnd(Pf[3], wr + oXpF,  64 * 1024);
  rnd(Pb[3], wr + oXpB,  64 * 1024);
  rnd(Pf[4], wr + oDtF,  1024 * 32);
  rnd(Pb[4], wr + oDtB,  1024 * 32);
  rnd(Pf[8], wr + oOutF, 512 * 1024);
  rnd(Pb[8], wr + oOutB, 512 * 1024);
  rnd(ffn_w1, wr + oF1,  2048 * 512);
  rnd(ffn_w2, wr + oF2,  512 * 2048);

  auto run_block = [&](const float* const* P, float* mout, int dir,
                       const float* w_in, const float* w_xp,
                       const float* w_dt, const float* w_out) {
    gemm_tc<0,0><<<dim3(kDXZ / 64, rowsY), blk>>>(xr, kDM, w_in, nullptr,
                                                  (float*)p_xz, kT, kDXZ, kDM);
    conv_silu_k<<<(kT * kDI) / 256, dim3(256)>>>(P[1], P[2], dir);
    gemm_tc<0,1><<<dim3(kDBC / 64, rowsY), blk>>>((const float*)p_xc, kDI, w_xp,
                                                  nullptr, (float*)p_dbc, kT, kDBC, kDI);
    gemm_tc<1,0><<<dim3(kDI / 64, rowsY), blk>>>((const float*)p_dbc, kDBC, w_dt,
                                                 P[5], (float*)p_dt, kT, kDI, kR);
    scan_k<<<512, dim3(256)>>>(P[6], P[7], dir);
    gemm_tc<0,0><<<dim3(kDM / 64, rowsY), blk>>>((const float*)p_y, kDI, w_out,
                                                 nullptr, mout, kT, kDM, kDI);
  };

  run_block(Pf, (float*)p_mf, +1, wr + oInF, wr + oXpF, wr + oDtF, wr + oOutF);
  run_block(Pb, (float*)p_mb, -1, wr + oInB, wr + oXpB, wr + oDtB, wr + oOutB);

  ln_combine_k<<<kT / 8, dim3(256)>>>(x, ln_f_g, ln_f_b, ln_b_g, ln_b_b);

  gemm_tc<2,1><<<dim3(kFF / 64, rowsY), blk>>>((const float*)p_h, kDM, wr + oF1,
                                               ffn_b1, (float*)p_xz, kT, kFF, kDM);
  gemm_tc<3,0><<<dim3(kDM / 64, rowsY), blk>>>((const float*)p_xz, kFF, wr + oF2,
                                               ffn_b2, (float*)p_mf, kT, kDM, kFF);

  ln_final_k<<<kT / 8, dim3(256)>>>((const float*)p_mf, ln_ff_g, ln_ff_b, out);
}

// round 10
// speedup vs baseline: 1.0066x; 1.0027x over previous
#include <cuda_runtime.h>
#include <cstdint>

// ---------------------------------------------------------------------------
// BiMambaLayer on GB300 — Round 8: R4 base (best passing) with ldmatrix
// fragment loads (LDSM x4/x2) replacing 96 scalar LDS.32 per warp per K-tile.
// tcgen05 is unavailable (toolchain targets sm_103 without 'a' features).
// ---------------------------------------------------------------------------

namespace {
constexpr int kB   = 8;
constexpr int kL   = 4096;
constexpr int kDM  = 512;
constexpr int kDI  = 1024;
constexpr int kDXZ = 2048;
constexpr int kN   = 16;
constexpr int kR   = 32;
constexpr int kDBC = 64;
constexpr int kFF  = 2048;
constexpr int kT   = kB * kL;
}

__device__ float g_xz [(size_t)kT * kDXZ];
__device__ float g_xc [(size_t)kT * kDI];
__device__ float g_dbc[(size_t)kT * kDBC];
__device__ float g_dt [(size_t)kT * kDI];
__device__ float g_y  [(size_t)kT * kDI];
__device__ float g_mf [(size_t)kT * kDM];
__device__ float g_mb [(size_t)kT * kDM];
__device__ float g_h  [(size_t)kT * kDM];

__device__ __forceinline__ uint32_t f2tf32(float x) {
  uint32_t r;
  asm("cvt.rna.tf32.f32 %0, %1;" : "=r"(r) : "f"(x));
  return r;
}

__device__ __forceinline__ void mma_tf32(float* d,
    uint32_t a0, uint32_t a1, uint32_t a2, uint32_t a3,
    uint32_t b0, uint32_t b1)
{
  asm volatile(
    "mma.sync.aligned.m16n8k8.row.col.f32.tf32.tf32.f32 "
    "{%0,%1,%2,%3}, {%4,%5,%6,%7}, {%8,%9}, {%0,%1,%2,%3};\n"
    : "+f"(d[0]), "+f"(d[1]), "+f"(d[2]), "+f"(d[3])
    : "r"(a0), "r"(a1), "r"(a2), "r"(a3), "r"(b0), "r"(b1));
}

__device__ __forceinline__ void ldsm4(uint32_t* r, uint32_t addr) {
  asm volatile(
    "ldmatrix.sync.aligned.m8n8.x4.shared.b16 {%0,%1,%2,%3}, [%4];"
    : "=r"(r[0]), "=r"(r[1]), "=r"(r[2]), "=r"(r[3]) : "r"(addr));
}
__device__ __forceinline__ void ldsm2(uint32_t& r0, uint32_t& r1, uint32_t addr) {
  asm volatile(
    "ldmatrix.sync.aligned.m8n8.x2.shared.b16 {%0,%1}, [%2];"
    : "=r"(r0), "=r"(r1) : "r"(addr));
}

// ---------------------------------------------------------------------------
// C[M,N] = A[M,K](row stride lda) * W[N,K]^T (+ epilogue)
// EPI: 0 none, 1 softplus(+bias), 2 gelu(+bias), 3 +bias
// 128 threads = 4 warps (2x2), warp tile 64x32.
// smem: plain [row][k] tf32 layout, row stride ST=36 words.
// Fragment loads via ldmatrix (LDSM): per warp per K-tile 32 LDSM vs 96 LDS.
// Requires M%128==0, N%64==0, K%32==0.
// ---------------------------------------------------------------------------
template<int EPI>
__global__ void __launch_bounds__(128, 3) gemm_tc(
    const float* __restrict__ A, int lda,
    const float* __restrict__ W,
    const float* __restrict__ bias,
    float* __restrict__ C, int M, int N, int K)
{
  constexpr int BM = 128, BN = 64, BK = 32, ST = 36;
  __shared__ uint32_t As[BM * ST];
  __shared__ uint32_t Ws[BN * ST];

  const int tid  = threadIdx.x;
  const int lane = tid & 31;
  const int wid  = tid >> 5;
  const int wm   = (wid & 1) * 64;
  const int wn   = (wid >> 1) * 32;
  const size_t bm = (size_t)blockIdx.y * BM;
  const int bn   = blockIdx.x * BN;
  const int g4   = lane >> 2;
  const int t4   = lane & 3;

  float acc[4][4][4];
  #pragma unroll
  for (int i = 0; i < 4; i++)
    #pragma unroll
    for (int j = 0; j < 4; j++)
      #pragma unroll
      for (int c = 0; c < 4; c++) acc[i][j][c] = 0.f;

  // Loader geometry (identical to R4): 8 A-float4 + 4 W-float4 per thread.
  const int ldR = tid >> 3;            // 0..15
  const int ldC = (tid & 7) << 2;      // k-col 0,4,..,28

  float4 aR[8];
  float4 wR[4];

  auto ldg_tiles = [&](int k0) {
    #pragma unroll
    for (int i = 0; i < 8; i++) {
      int r = ldR + 16 * i;
      aR[i] = *reinterpret_cast<const float4*>(&A[(bm + r) * (size_t)lda + k0 + ldC]);
    }
    #pragma unroll
    for (int i = 0; i < 4; i++) {
      int r = ldR + 16 * i;
      wR[i] = *reinterpret_cast<const float4*>(&W[(size_t)(bn + r) * K + k0 + ldC]);
    }
  };

  auto sts_tiles = [&]() {
    #pragma unroll
    for (int i = 0; i < 8; i++) {
      int r = ldR + 16 * i;
      uint4 v = { f2tf32(aR[i].x), f2tf32(aR[i].y), f2tf32(aR[i].z), f2tf32(aR[i].w) };
      *reinterpret_cast<uint4*>(&As[r * ST + ldC]) = v;
    }
    #pragma unroll
    for (int i = 0; i < 4; i++) {
      int r = ldR + 16 * i;
      uint4 v = { f2tf32(wR[i].x), f2tf32(wR[i].y), f2tf32(wR[i].z), f2tf32(wR[i].w) };
      *reinterpret_cast<uint4*>(&Ws[r * ST + ldC]) = v;
    }
  };

  // --- ldmatrix per-lane addresses (computed once) ---
  // A x4: matrices m0..m3 = {rows+0..7, rows+8..15} x {k+0..3, k+4..7};
  //   lanes 0-7 -> m0 rows, 8-15 -> m1, 16-23 -> m2, 24-31 -> m3.
  // B x2: m0 = n-rows+0..7 @ k+0..3, m1 = same rows @ k+4..7 (lanes 0-15).
  const int mrow = lane & 7;
  const int mat  = lane >> 3;
  uint32_t aAddr[4], bAddr[4];
  {
    const uint32_t asB = (uint32_t)__cvta_generic_to_shared(As);
    const uint32_t wsB = (uint32_t)__cvta_generic_to_shared(Ws);
    #pragma unroll
    for (int mi = 0; mi < 4; mi++)
      aAddr[mi] = asB +
        (uint32_t)(((wm + mi * 16 + (mat & 1) * 8 + mrow) * ST + (mat >> 1) * 4) * 4);
    #pragma unroll
    for (int nj = 0; nj < 4; nj++)
      bAddr[nj] = wsB +
        (uint32_t)(((wn + nj * 8 + mrow) * ST + (mat & 1) * 4) * 4);
  }

  ldg_tiles(0);
  sts_tiles();
  __syncthreads();

  for (int k0 = 0; k0 < K; k0 += BK) {
    const bool more = (k0 + BK) < K;
    if (more) ldg_tiles(k0 + BK);

    #pragma unroll
    for (int kk = 0; kk < 4; kk++) {
      uint32_t a[4][4];
      uint32_t b[4][2];
      #pragma unroll
      for (int mi = 0; mi < 4; mi++)
        ldsm4(a[mi], aAddr[mi] + (uint32_t)(kk * 32));
      #pragma unroll
      for (int nj = 0; nj < 4; nj++)
        ldsm2(b[nj][0], b[nj][1], bAddr[nj] + (uint32_t)(kk * 32));
      #pragma unroll
      for (int mi = 0; mi < 4; mi++)
        #pragma unroll
        for (int nj = 0; nj < 4; nj++)
          mma_tf32(acc[mi][nj], a[mi][0], a[mi][1], a[mi][2], a[mi][3],
                   b[nj][0], b[nj][1]);
    }
    __syncthreads();
    if (more) {
      sts_tiles();
      __syncthreads();
    }
  }

  // Epilogue (identical to R4)
  #pragma unroll
  for (int mi = 0; mi < 4; mi++) {
    #pragma unroll
    for (int nj = 0; nj < 4; nj++) {
      size_t r0 = bm + wm + mi * 16 + g4;
      int c0 = bn + wn + nj * 8 + 2 * t4;
      #pragma unroll
      for (int half = 0; half < 2; half++) {
        size_t row = r0 + half * 8;
        float2 v;
        v.x = acc[mi][nj][half * 2 + 0];
        v.y = acc[mi][nj][half * 2 + 1];
        if (EPI == 1) {
          v.x += __ldg(&bias[c0]);     v.y += __ldg(&bias[c0 + 1]);
          v.x = fmaxf(v.x, 0.f) + log1pf(__expf(-fabsf(v.x)));
          v.y = fmaxf(v.y, 0.f) + log1pf(__expf(-fabsf(v.y)));
        } else if (EPI == 2) {
          v.x += __ldg(&bias[c0]);     v.y += __ldg(&bias[c0 + 1]);
          float tx = tanhf(0.7978845608028654f * (v.x + 0.044715f * v.x * v.x * v.x));
          float ty = tanhf(0.7978845608028654f * (v.y + 0.044715f * v.y * v.y * v.y));
          v.x = 0.5f * v.x * (1.f + tx);
          v.y = 0.5f * v.y * (1.f + ty);
        } else if (EPI == 3) {
          v.x += __ldg(&bias[c0]);     v.y += __ldg(&bias[c0 + 1]);
        }
        *reinterpret_cast<float2*>(&C[row * N + c0]) = v;
      }
    }
  }
}

// ---------------------------------------------------------------------------
// Depthwise causal conv (k=4) + bias + silu; dir=+1 fwd, -1 bwd (mirrored).
// ---------------------------------------------------------------------------
__global__ void conv_silu_k(const float* __restrict__ cw,
                            const float* __restrict__ cb, int dir)
{
  int i = blockIdx.x * blockDim.x + threadIdx.x;
  int d = i & (kDI - 1);
  int tok = i >> 10;
  int pos = tok & (kL - 1);
  float acc = __ldg(&cb[d]);
  #pragma unroll
  for (int j = 0; j < 4; j++) {
    int o = (dir > 0) ? (j - 3) : (3 - j);
    int p = pos + o;
    if (p >= 0 && p < kL)
      acc = fmaf(__ldg(&cw[d * 4 + j]), g_xz[(size_t)(tok + o) * kDXZ + d], acc);
  }
  g_xc[i] = acc / (1.f + __expf(-acc));
}

// ---------------------------------------------------------------------------
// Selective scan, warp = 2 channels (16 state lanes each).
// ---------------------------------------------------------------------------
__global__ void scan_k(const float* __restrict__ A_log,
                       const float* __restrict__ Dp, int dir)
{
  int gw   = (blockIdx.x * blockDim.x + threadIdx.x) >> 5;
  int lane = threadIdx.x & 31;
  int half = lane >> 4;
  int n    = lane & 15;
  int ch   = gw * 2 + half;
  int b    = ch >> 10;
  int d    = ch & (kDI - 1);

  float A  = -__expf(__ldg(&A_log[d * kN + n]));
  float Dv = __ldg(&Dp[d]);
  float h  = 0.f;
  const size_t tokbase = (size_t)b * kL;

  for (int u = 0; u < kL; ++u) {
    int pos = (dir > 0) ? u : (kL - 1 - u);
    size_t tok = tokbase + pos;
    float dtv = g_dt [tok * kDI  + d];
    float xv  = g_xc [tok * kDI  + d];
    float Bv  = g_dbc[tok * kDBC + kR + n];
    float Cv  = g_dbc[tok * kDBC + kR + kN + n];
    float a   = __expf(dtv * A);
    h = fmaf(a, h, dtv * xv * Bv);
    float p = h * Cv;
    p += __shfl_xor_sync(0xffffffffu, p, 1);
    p += __shfl_xor_sync(0xffffffffu, p, 2);
    p += __shfl_xor_sync(0xffffffffu, p, 4);
    p += __shfl_xor_sync(0xffffffffu, p, 8);
    if (n == 0) {
      float zv = g_xz[tok * kDXZ + kDI + d];
      float sz = zv / (1.f + __expf(-zv));
      g_y[tok * kDI + d] = (p + xv * Dv) * sz;
    }
  }
}

// ---------------------------------------------------------------------------
// LayerNorms
// ---------------------------------------------------------------------------
__device__ __forceinline__ float warp_sum(float v) {
  v += __shfl_xor_sync(0xffffffffu, v, 16);
  v += __shfl_xor_sync(0xffffffffu, v, 8);
  v += __shfl_xor_sync(0xffffffffu, v, 4);
  v += __shfl_xor_sync(0xffffffffu, v, 2);
  v += __shfl_xor_sync(0xffffffffu, v, 1);
  return v;
}

__global__ void ln_combine_k(const float* __restrict__ x,
    const float* __restrict__ gf, const float* __restrict__ bf,
    const float* __restrict__ gb, const float* __restrict__ bb)
{
  int row  = blockIdx.x * (blockDim.x >> 5) + (threadIdx.x >> 5);
  int lane = threadIdx.x & 31;
  const float* xr = x    + (size_t)row * kDM;
  const float* fr = g_mf + (size_t)row * kDM;
  const float* br = g_mb + (size_t)row * kDM;

  float u[16], v[16];
  float su = 0.f, sv = 0.f;
  #pragma unroll
  for (int k = 0; k < 4; k++) {
    int idx = (k * 32 + lane) * 4;
    float4 a  = *reinterpret_cast<const float4*>(xr + idx);
    float4 m1 = *reinterpret_cast<const float4*>(fr + idx);
    float4 m2 = *reinterpret_cast<const float4*>(br + idx);
    u[k*4+0]=a.x+m1.x; u[k*4+1]=a.y+m1.y; u[k*4+2]=a.z+m1.z; u[k*4+3]=a.w+m1.w;
    v[k*4+0]=a.x+m2.x; v[k*4+1]=a.y+m2.y; v[k*4+2]=a.z+m2.z; v[k*4+3]=a.w+m2.w;
    #pragma unroll
    for (int c = 0; c < 4; c++) { su += u[k*4+c]; sv += v[k*4+c]; }
  }
  float muU = warp_sum(su) * (1.f / kDM);
  float muV = warp_sum(sv) * (1.f / kDM);
  float qu = 0.f, qv = 0.f;
  #pragma unroll
  for (int c = 0; c < 16; c++) {
    float du = u[c] - muU, dv = v[c] - muV;
    qu += du * du; qv += dv * dv;
  }
  float rsU = rsqrtf(warp_sum(qu) * (1.f / kDM) + 1e-5f);
  float rsV = rsqrtf(warp_sum(qv) * (1.f / kDM) + 1e-5f);

  float* hr = g_h + (size_t)row * kDM;
  #pragma unroll
  for (int k = 0; k < 4; k++) {
    int idx = (k * 32 + lane) * 4;
    float4 o;
    #pragma unroll
    for (int c = 0; c < 4; c++) {
      int f = idx + c;
      float a = (u[k*4+c] - muU) * rsU * __ldg(&gf[f]) + __ldg(&bf[f]);
      float bvv = (v[k*4+c] - muV) * rsV * __ldg(&gb[f]) + __ldg(&bb[f]);
      ((float*)&o)[c] = 0.5f * (a + bvv);
    }
    *reinterpret_cast<float4*>(hr + idx) = o;
  }
}

__global__ void ln_final_k(const float* __restrict__ ff,
    const float* __restrict__ g, const float* __restrict__ bia,
    float* __restrict__ out)
{
  int row  = blockIdx.x * (blockDim.x >> 5) + (threadIdx.x >> 5);
  int lane = threadIdx.x & 31;
  const float* hr = g_h + (size_t)row * kDM;
  const float* fr = ff  + (size_t)row * kDM;

  float u[16];
  float su = 0.f;
  #pragma unroll
  for (int k = 0; k < 4; k++) {
    int idx = (k * 32 + lane) * 4;
    float4 a  = *reinterpret_cast<const float4*>(hr + idx);
    float4 m1 = *reinterpret_cast<const float4*>(fr + idx);
    u[k*4+0]=a.x+m1.x; u[k*4+1]=a.y+m1.y; u[k*4+2]=a.z+m1.z; u[k*4+3]=a.w+m1.w;
    #pragma unroll
    for (int c = 0; c < 4; c++) su += u[k*4+c];
  }
  float mu = warp_sum(su) * (1.f / kDM);
  float q = 0.f;
  #pragma unroll
  for (int c = 0; c < 16; c++) { float d = u[c] - mu; q += d * d; }
  float rs = rsqrtf(warp_sum(q) * (1.f / kDM) + 1e-5f);

  float* orow = out + (size_t)row * kDM;
  #pragma unroll
  for (int k = 0; k < 4; k++) {
    int idx = (k * 32 + lane) * 4;
    float4 o;
    #pragma unroll
    for (int c = 0; c < 4; c++) {
      int f = idx + c;
      ((float*)&o)[c] = (u[k*4+c] - mu) * rs * __ldg(&g[f]) + __ldg(&bia[f]);
    }
    *reinterpret_cast<float4*>(orow + idx) = o;
  }
}

// ---------------------------------------------------------------------------
// Launch
// ---------------------------------------------------------------------------
extern "C" void kernel_launch(void* const* d_in, const int* in_sizes, int n_in,
                              void* d_out, int out_size)
{
  const float* x = (const float*)d_in[0];
  const float* const* Pf = (const float* const*)&d_in[1];
  const float* const* Pb = (const float* const*)&d_in[10];
  const float* ln_f_g  = (const float*)d_in[19];
  const float* ln_f_b  = (const float*)d_in[20];
  const float* ln_b_g  = (const float*)d_in[21];
  const float* ln_b_b  = (const float*)d_in[22];
  const float* ln_ff_g = (const float*)d_in[23];
  const float* ln_ff_b = (const float*)d_in[24];
  const float* ffn_w1  = (const float*)d_in[25];
  const float* ffn_b1  = (const float*)d_in[26];
  const float* ffn_w2  = (const float*)d_in[27];
  const float* ffn_b2  = (const float*)d_in[28];
  float* out = (float*)d_out;

  void *p_xz, *p_xc, *p_dbc, *p_dt, *p_y, *p_mf, *p_mb, *p_h;
  cudaGetSymbolAddress(&p_xz,  g_xz);
  cudaGetSymbolAddress(&p_xc,  g_xc);
  cudaGetSymbolAddress(&p_dbc, g_dbc);
  cudaGetSymbolAddress(&p_dt,  g_dt);
  cudaGetSymbolAddress(&p_y,   g_y);
  cudaGetSymbolAddress(&p_mf,  g_mf);
  cudaGetSymbolAddress(&p_mb,  g_mb);
  cudaGetSymbolAddress(&p_h,   g_h);

  const dim3 blk(128);
  const int rowsY = kT / 128;   // 256

  auto run_block = [&](const float* const* P, float* mout, int dir) {
    gemm_tc<0><<<dim3(kDXZ / 64, rowsY), blk>>>(x, kDM, P[0], nullptr,
                                                (float*)p_xz, kT, kDXZ, kDM);
    conv_silu_k<<<(kT * kDI) / 256, dim3(256)>>>(P[1], P[2], dir);
    gemm_tc<0><<<dim3(kDBC / 64, rowsY), blk>>>((const float*)p_xc, kDI, P[3],
                                                nullptr, (float*)p_dbc, kT, kDBC, kDI);
    gemm_tc<1><<<dim3(kDI / 64, rowsY), blk>>>((const float*)p_dbc, kDBC, P[4],
                                               P[5], (float*)p_dt, kT, kDI, kR);
    scan_k<<<512, dim3(256)>>>(P[6], P[7], dir);
    gemm_tc<0><<<dim3(kDM / 64, rowsY), blk>>>((const float*)p_y, kDI, P[8],
                                               nullptr, mout, kT, kDM, kDI);
  };

  run_block(Pf, (float*)p_mf, +1);
  run_block(Pb, (float*)p_mb, -1);

  ln_combine_k<<<kT / 8, dim3(256)>>>(x, ln_f_g, ln_f_b, ln_b_g, ln_b_b);

  gemm_tc<2><<<dim3(kFF / 64, rowsY), blk>>>((const float*)p_h, kDM, ffn_w1,
                                             ffn_b1, (float*)p_xz, kT, kFF, kDM);
  gemm_tc<3><<<dim3(kDM / 64, rowsY), blk>>>((const float*)p_xz, kFF, ffn_w2,
                                             ffn_b2, (float*)p_mf, kT, kDM, kFF);

  ln_final_k<<<kT / 8, dim3(256)>>>((const float*)p_mf, ln_ff_g, ln_ff_b, out);
}

// round 11
// speedup vs baseline: 1.0494x; 1.0425x over previous
#include <cuda_runtime.h>
#include <cuda_fp16.h>
#include <cstdint>

// ---------------------------------------------------------------------------
// BiMambaLayer on GB300 — Round 9: R8 base with the MMA switched from
// tf32 m16n8k8 (slow fallback HMMA) to native fp16 m16n8k16 (fp32 accum).
// Same 10-bit mantissa as tf32 => same numerics class; half the MMA and
// LDSM instructions, full-rate HMMA.
// ---------------------------------------------------------------------------

namespace {
constexpr int kB   = 8;
constexpr int kL   = 4096;
constexpr int kDM  = 512;
constexpr int kDI  = 1024;
constexpr int kDXZ = 2048;
constexpr int kN   = 16;
constexpr int kR   = 32;
constexpr int kDBC = 64;
constexpr int kFF  = 2048;
constexpr int kT   = kB * kL;
}

__device__ float g_xz [(size_t)kT * kDXZ];
__device__ float g_xc [(size_t)kT * kDI];
__device__ float g_dbc[(size_t)kT * kDBC];
__device__ float g_dt [(size_t)kT * kDI];
__device__ float g_y  [(size_t)kT * kDI];
__device__ float g_mf [(size_t)kT * kDM];
__device__ float g_mb [(size_t)kT * kDM];
__device__ float g_h  [(size_t)kT * kDM];

__device__ __forceinline__ void mma_f16(float* d,
    uint32_t a0, uint32_t a1, uint32_t a2, uint32_t a3,
    uint32_t b0, uint32_t b1)
{
  asm volatile(
    "mma.sync.aligned.m16n8k16.row.col.f32.f16.f16.f32 "
    "{%0,%1,%2,%3}, {%4,%5,%6,%7}, {%8,%9}, {%0,%1,%2,%3};\n"
    : "+f"(d[0]), "+f"(d[1]), "+f"(d[2]), "+f"(d[3])
    : "r"(a0), "r"(a1), "r"(a2), "r"(a3), "r"(b0), "r"(b1));
}

__device__ __forceinline__ void ldsm4(uint32_t* r, uint32_t addr) {
  asm volatile(
    "ldmatrix.sync.aligned.m8n8.x4.shared.b16 {%0,%1,%2,%3}, [%4];"
    : "=r"(r[0]), "=r"(r[1]), "=r"(r[2]), "=r"(r[3]) : "r"(addr));
}
__device__ __forceinline__ void ldsm2(uint32_t& r0, uint32_t& r1, uint32_t addr) {
  asm volatile(
    "ldmatrix.sync.aligned.m8n8.x2.shared.b16 {%0,%1}, [%2];"
    : "=r"(r0), "=r"(r1) : "r"(addr));
}

__device__ __forceinline__ uint32_t pack_h2(float a, float b) {
  __half2 h = __floats2half2_rn(a, b);
  return *reinterpret_cast<uint32_t*>(&h);
}

// ---------------------------------------------------------------------------
// C[M,N] = A[M,K](row stride lda) * W[N,K]^T (+ epilogue)
// EPI: 0 none, 1 softplus(+bias), 2 gelu(+bias), 3 +bias
// 128 threads = 4 warps (2x2), warp tile 64x32, fp16 operands, fp32 accum.
// smem: [row][k] fp16 layout, row stride ST2=40 halves (80B, 16B-aligned,
// ldmatrix conflict-free: row banks {0,20,8,28,16,4,24,12}).
// Requires M%128==0, N%64==0, K%32==0.
// ---------------------------------------------------------------------------
template<int EPI>
__global__ void __launch_bounds__(128, 3) gemm_tc(
    const float* __restrict__ A, int lda,
    const float* __restrict__ W,
    const float* __restrict__ bias,
    float* __restrict__ C, int M, int N, int K)
{
  constexpr int BM = 128, BN = 64, BK = 32, ST2 = 40;
  __shared__ __half As[BM * ST2];
  __shared__ __half Ws[BN * ST2];

  const int tid  = threadIdx.x;
  const int lane = tid & 31;
  const int wid  = tid >> 5;
  const int wm   = (wid & 1) * 64;
  const int wn   = (wid >> 1) * 32;
  const size_t bm = (size_t)blockIdx.y * BM;
  const int bn   = blockIdx.x * BN;
  const int g4   = lane >> 2;
  const int t4   = lane & 3;

  float acc[4][4][4];
  #pragma unroll
  for (int i = 0; i < 4; i++)
    #pragma unroll
    for (int j = 0; j < 4; j++)
      #pragma unroll
      for (int c = 0; c < 4; c++) acc[i][j][c] = 0.f;

  // Loader geometry (identical to R4/R8): 8 A-float4 + 4 W-float4 per thread.
  const int ldR = tid >> 3;            // 0..15
  const int ldC = (tid & 7) << 2;      // k-col 0,4,..,28 (fp16 units)

  float4 aR[8];
  float4 wR[4];

  auto ldg_tiles = [&](int k0) {
    #pragma unroll
    for (int i = 0; i < 8; i++) {
      int r = ldR + 16 * i;
      aR[i] = *reinterpret_cast<const float4*>(&A[(bm + r) * (size_t)lda + k0 + ldC]);
    }
    #pragma unroll
    for (int i = 0; i < 4; i++) {
      int r = ldR + 16 * i;
      wR[i] = *reinterpret_cast<const float4*>(&W[(size_t)(bn + r) * K + k0 + ldC]);
    }
  };

  auto sts_tiles = [&]() {
    #pragma unroll
    for (int i = 0; i < 8; i++) {
      int r = ldR + 16 * i;
      uint2 v = { pack_h2(aR[i].x, aR[i].y), pack_h2(aR[i].z, aR[i].w) };
      *reinterpret_cast<uint2*>(&As[r * ST2 + ldC]) = v;
    }
    #pragma unroll
    for (int i = 0; i < 4; i++) {
      int r = ldR + 16 * i;
      uint2 v = { pack_h2(wR[i].x, wR[i].y), pack_h2(wR[i].z, wR[i].w) };
      *reinterpret_cast<uint2*>(&Ws[r * ST2 + ldC]) = v;
    }
  };

  // --- ldmatrix per-lane addresses (computed once) ---
  // A x4 (per 16-row tile, per k16 step): m0 = rows+0..7 k0..7,
  //   m1 = rows+8..15 k0..7, m2 = rows+0..7 k8..15, m3 = rows+8..15 k8..15.
  // B x2 (per 8-col n tile): m0 = n-rows k0..7, m1 = same rows k8..15.
  const int mrow = lane & 7;
  const int mat  = lane >> 3;
  uint32_t aAddr[4], bAddr[4];
  {
    const uint32_t asB = (uint32_t)__cvta_generic_to_shared(As);
    const uint32_t wsB = (uint32_t)__cvta_generic_to_shared(Ws);
    #pragma unroll
    for (int mi = 0; mi < 4; mi++)
      aAddr[mi] = asB + (uint32_t)(((wm + mi * 16 + (mat & 1) * 8 + mrow) * ST2
                                    + (mat >> 1) * 8) * 2);
    #pragma unroll
    for (int nj = 0; nj < 4; nj++)
      bAddr[nj] = wsB + (uint32_t)(((wn + nj * 8 + mrow) * ST2
                                    + (mat & 1) * 8) * 2);
  }

  ldg_tiles(0);
  sts_tiles();
  __syncthreads();

  for (int k0 = 0; k0 < K; k0 += BK) {
    const bool more = (k0 + BK) < K;
    if (more) ldg_tiles(k0 + BK);

    #pragma unroll
    for (int kk = 0; kk < 2; kk++) {          // two k16 steps per K-tile
      uint32_t a[4][4];
      uint32_t b[4][2];
      #pragma unroll
      for (int mi = 0; mi < 4; mi++)
        ldsm4(a[mi], aAddr[mi] + (uint32_t)(kk * 32));   // +16 halves
      #pragma unroll
      for (int nj = 0; nj < 4; nj++)
        ldsm2(b[nj][0], b[nj][1], bAddr[nj] + (uint32_t)(kk * 32));
      #pragma unroll
      for (int mi = 0; mi < 4; mi++)
        #pragma unroll
        for (int nj = 0; nj < 4; nj++)
          mma_f16(acc[mi][nj], a[mi][0], a[mi][1], a[mi][2], a[mi][3],
                  b[nj][0], b[nj][1]);
    }
    __syncthreads();
    if (more) {
      sts_tiles();
      __syncthreads();
    }
  }

  // Epilogue (identical to R4/R8; C fragment layout same for k16 shape)
  #pragma unroll
  for (int mi = 0; mi < 4; mi++) {
    #pragma unroll
    for (int nj = 0; nj < 4; nj++) {
      size_t r0 = bm + wm + mi * 16 + g4;
      int c0 = bn + wn + nj * 8 + 2 * t4;
      #pragma unroll
      for (int half = 0; half < 2; half++) {
        size_t row = r0 + half * 8;
        float2 v;
        v.x = acc[mi][nj][half * 2 + 0];
        v.y = acc[mi][nj][half * 2 + 1];
        if (EPI == 1) {
          v.x += __ldg(&bias[c0]);     v.y += __ldg(&bias[c0 + 1]);
          v.x = fmaxf(v.x, 0.f) + log1pf(__expf(-fabsf(v.x)));
          v.y = fmaxf(v.y, 0.f) + log1pf(__expf(-fabsf(v.y)));
        } else if (EPI == 2) {
          v.x += __ldg(&bias[c0]);     v.y += __ldg(&bias[c0 + 1]);
          float tx = tanhf(0.7978845608028654f * (v.x + 0.044715f * v.x * v.x * v.x));
          float ty = tanhf(0.7978845608028654f * (v.y + 0.044715f * v.y * v.y * v.y));
          v.x = 0.5f * v.x * (1.f + tx);
          v.y = 0.5f * v.y * (1.f + ty);
        } else if (EPI == 3) {
          v.x += __ldg(&bias[c0]);     v.y += __ldg(&bias[c0 + 1]);
        }
        *reinterpret_cast<float2*>(&C[row * N + c0]) = v;
      }
    }
  }
}

// ---------------------------------------------------------------------------
// Depthwise causal conv (k=4) + bias + silu; dir=+1 fwd, -1 bwd (mirrored).
// ---------------------------------------------------------------------------
__global__ void conv_silu_k(const float* __restrict__ cw,
                            const float* __restrict__ cb, int dir)
{
  int i = blockIdx.x * blockDim.x + threadIdx.x;
  int d = i & (kDI - 1);
  int tok = i >> 10;
  int pos = tok & (kL - 1);
  float acc = __ldg(&cb[d]);
  #pragma unroll
  for (int j = 0; j < 4; j++) {
    int o = (dir > 0) ? (j - 3) : (3 - j);
    int p = pos + o;
    if (p >= 0 && p < kL)
      acc = fmaf(__ldg(&cw[d * 4 + j]), g_xz[(size_t)(tok + o) * kDXZ + d], acc);
  }
  g_xc[i] = acc / (1.f + __expf(-acc));
}

// ---------------------------------------------------------------------------
// Selective scan, warp = 2 channels (16 state lanes each).
// ---------------------------------------------------------------------------
__global__ void scan_k(const float* __restrict__ A_log,
                       const float* __restrict__ Dp, int dir)
{
  int gw   = (blockIdx.x * blockDim.x + threadIdx.x) >> 5;
  int lane = threadIdx.x & 31;
  int half = lane >> 4;
  int n    = lane & 15;
  int ch   = gw * 2 + half;
  int b    = ch >> 10;
  int d    = ch & (kDI - 1);

  float A  = -__expf(__ldg(&A_log[d * kN + n]));
  float Dv = __ldg(&Dp[d]);
  float h  = 0.f;
  const size_t tokbase = (size_t)b * kL;

  for (int u = 0; u < kL; ++u) {
    int pos = (dir > 0) ? u : (kL - 1 - u);
    size_t tok = tokbase + pos;
    float dtv = g_dt [tok * kDI  + d];
    float xv  = g_xc [tok * kDI  + d];
    float Bv  = g_dbc[tok * kDBC + kR + n];
    float Cv  = g_dbc[tok * kDBC + kR + kN + n];
    float a   = __expf(dtv * A);
    h = fmaf(a, h, dtv * xv * Bv);
    float p = h * Cv;
    p += __shfl_xor_sync(0xffffffffu, p, 1);
    p += __shfl_xor_sync(0xffffffffu, p, 2);
    p += __shfl_xor_sync(0xffffffffu, p, 4);
    p += __shfl_xor_sync(0xffffffffu, p, 8);
    if (n == 0) {
      float zv = g_xz[tok * kDXZ + kDI + d];
      float sz = zv / (1.f + __expf(-zv));
      g_y[tok * kDI + d] = (p + xv * Dv) * sz;
    }
  }
}

// ---------------------------------------------------------------------------
// LayerNorms
// ---------------------------------------------------------------------------
__device__ __forceinline__ float warp_sum(float v) {
  v += __shfl_xor_sync(0xffffffffu, v, 16);
  v += __shfl_xor_sync(0xffffffffu, v, 8);
  v += __shfl_xor_sync(0xffffffffu, v, 4);
  v += __shfl_xor_sync(0xffffffffu, v, 2);
  v += __shfl_xor_sync(0xffffffffu, v, 1);
  return v;
}

__global__ void ln_combine_k(const float* __restrict__ x,
    const float* __restrict__ gf, const float* __restrict__ bf,
    const float* __restrict__ gb, const float* __restrict__ bb)
{
  int row  = blockIdx.x * (blockDim.x >> 5) + (threadIdx.x >> 5);
  int lane = threadIdx.x & 31;
  const float* xr = x    + (size_t)row * kDM;
  const float* fr = g_mf + (size_t)row * kDM;
  const float* br = g_mb + (size_t)row * kDM;

  float u[16], v[16];
  float su = 0.f, sv = 0.f;
  #pragma unroll
  for (int k = 0; k < 4; k++) {
    int idx = (k * 32 + lane) * 4;
    float4 a  = *reinterpret_cast<const float4*>(xr + idx);
    float4 m1 = *reinterpret_cast<const float4*>(fr + idx);
    float4 m2 = *reinterpret_cast<const float4*>(br + idx);
    u[k*4+0]=a.x+m1.x; u[k*4+1]=a.y+m1.y; u[k*4+2]=a.z+m1.z; u[k*4+3]=a.w+m1.w;
    v[k*4+0]=a.x+m2.x; v[k*4+1]=a.y+m2.y; v[k*4+2]=a.z+m2.z; v[k*4+3]=a.w+m2.w;
    #pragma unroll
    for (int c = 0; c < 4; c++) { su += u[k*4+c]; sv += v[k*4+c]; }
  }
  float muU = warp_sum(su) * (1.f / kDM);
  float muV = warp_sum(sv) * (1.f / kDM);
  float qu = 0.f, qv = 0.f;
  #pragma unroll
  for (int c = 0; c < 16; c++) {
    float du = u[c] - muU, dv = v[c] - muV;
    qu += du * du; qv += dv * dv;
  }
  float rsU = rsqrtf(warp_sum(qu) * (1.f / kDM) + 1e-5f);
  float rsV = rsqrtf(warp_sum(qv) * (1.f / kDM) + 1e-5f);

  float* hr = g_h + (size_t)row * kDM;
  #pragma unroll
  for (int k = 0; k < 4; k++) {
    int idx = (k * 32 + lane) * 4;
    float4 o;
    #pragma unroll
    for (int c = 0; c < 4; c++) {
      int f = idx + c;
      float a = (u[k*4+c] - muU) * rsU * __ldg(&gf[f]) + __ldg(&bf[f]);
      float bvv = (v[k*4+c] - muV) * rsV * __ldg(&gb[f]) + __ldg(&bb[f]);
      ((float*)&o)[c] = 0.5f * (a + bvv);
    }
    *reinterpret_cast<float4*>(hr + idx) = o;
  }
}

__global__ void ln_final_k(const float* __restrict__ ff,
    const float* __restrict__ g, const float* __restrict__ bia,
    float* __restrict__ out)
{
  int row  = blockIdx.x * (blockDim.x >> 5) + (threadIdx.x >> 5);
  int lane = threadIdx.x & 31;
  const float* hr = g_h + (size_t)row * kDM;
  const float* fr = ff  + (size_t)row * kDM;

  float u[16];
  float su = 0.f;
  #pragma unroll
  for (int k = 0; k < 4; k++) {
    int idx = (k * 32 + lane) * 4;
    float4 a  = *reinterpret_cast<const float4*>(hr + idx);
    float4 m1 = *reinterpret_cast<const float4*>(fr + idx);
    u[k*4+0]=a.x+m1.x; u[k*4+1]=a.y+m1.y; u[k*4+2]=a.z+m1.z; u[k*4+3]=a.w+m1.w;
    #pragma unroll
    for (int c = 0; c < 4; c++) su += u[k*4+c];
  }
  float mu = warp_sum(su) * (1.f / kDM);
  float q = 0.f;
  #pragma unroll
  for (int c = 0; c < 16; c++) { float d = u[c] - mu; q += d * d; }
  float rs = rsqrtf(warp_sum(q) * (1.f / kDM) + 1e-5f);

  float* orow = out + (size_t)row * kDM;
  #pragma unroll
  for (int k = 0; k < 4; k++) {
    int idx = (k * 32 + lane) * 4;
    float4 o;
    #pragma unroll
    for (int c = 0; c < 4; c++) {
      int f = idx + c;
      ((float*)&o)[c] = (u[k*4+c] - mu) * rs * __ldg(&g[f]) + __ldg(&bia[f]);
    }
    *reinterpret_cast<float4*>(orow + idx) = o;
  }
}

// ---------------------------------------------------------------------------
// Launch
// ---------------------------------------------------------------------------
extern "C" void kernel_launch(void* const* d_in, const int* in_sizes, int n_in,
                              void* d_out, int out_size)
{
  const float* x = (const float*)d_in[0];
  const float* const* Pf = (const float* const*)&d_in[1];
  const float* const* Pb = (const float* const*)&d_in[10];
  const float* ln_f_g  = (const float*)d_in[19];
  const float* ln_f_b  = (const float*)d_in[20];
  const float* ln_b_g  = (const float*)d_in[21];
  const float* ln_b_b  = (const float*)d_in[22];
  const float* ln_ff_g = (const float*)d_in[23];
  const float* ln_ff_b = (const float*)d_in[24];
  const float* ffn_w1  = (const float*)d_in[25];
  const float* ffn_b1  = (const float*)d_in[26];
  const float* ffn_w2  = (const float*)d_in[27];
  const float* ffn_b2  = (const float*)d_in[28];
  float* out = (float*)d_out;

  void *p_xz, *p_xc, *p_dbc, *p_dt, *p_y, *p_mf, *p_mb, *p_h;
  cudaGetSymbolAddress(&p_xz,  g_xz);
  cudaGetSymbolAddress(&p_xc,  g_xc);
  cudaGetSymbolAddress(&p_dbc, g_dbc);
  cudaGetSymbolAddress(&p_dt,  g_dt);
  cudaGetSymbolAddress(&p_y,   g_y);
  cudaGetSymbolAddress(&p_mf,  g_mf);
  cudaGetSymbolAddress(&p_mb,  g_mb);
  cudaGetSymbolAddress(&p_h,   g_h);

  const dim3 blk(128);
  const int rowsY = kT / 128;   // 256

  auto run_block = [&](const float* const* P, float* mout, int dir) {
    gemm_tc<0><<<dim3(kDXZ / 64, rowsY), blk>>>(x, kDM, P[0], nullptr,
                                                (float*)p_xz, kT, kDXZ, kDM);
    conv_silu_k<<<(kT * kDI) / 256, dim3(256)>>>(P[1], P[2], dir);
    gemm_tc<0><<<dim3(kDBC / 64, rowsY), blk>>>((const float*)p_xc, kDI, P[3],
                                                nullptr, (float*)p_dbc, kT, kDBC, kDI);
    gemm_tc<1><<<dim3(kDI / 64, rowsY), blk>>>((const float*)p_dbc, kDBC, P[4],
                                               P[5], (float*)p_dt, kT, kDI, kR);
    scan_k<<<512, dim3(256)>>>(P[6], P[7], dir);
    gemm_tc<0><<<dim3(kDM / 64, rowsY), blk>>>((const float*)p_y, kDI, P[8],
                                               nullptr, mout, kT, kDM, kDI);
  };

  run_block(Pf, (float*)p_mf, +1);
  run_block(Pb, (float*)p_mb, -1);

  ln_combine_k<<<kT / 8, dim3(256)>>>(x, ln_f_g, ln_f_b, ln_b_g, ln_b_b);

  gemm_tc<2><<<dim3(kFF / 64, rowsY), blk>>>((const float*)p_h, kDM, ffn_w1,
                                             ffn_b1, (float*)p_xz, kT, kFF, kDM);
  gemm_tc<3><<<dim3(kDM / 64, rowsY), blk>>>((const float*)p_xz, kFF, ffn_w2,
                                             ffn_b2, (float*)p_mf, kT, kDM, kFF);

  ln_final_k<<<kT / 8, dim3(256)>>>((const float*)p_mf, ln_ff_g, ln_ff_b, out);
}

// round 12
// speedup vs baseline: 1.0808x; 1.0300x over previous
#include <cuda_runtime.h>
#include <cuda_fp16.h>
#include <cstdint>

// ---------------------------------------------------------------------------
// BiMambaLayer on GB300 — Round 10: fp16 end-to-end storage.
// R9 GEMM mainloop (ldmatrix + mma.m16n8k16.f16, fp32 accum) unchanged;
// all GEMM operands now live in fp16 in GMEM (half the LDG/STS and traffic),
// elementwise kernels read/write fp16. Output-critical tensors stay fp32.
// ---------------------------------------------------------------------------

namespace {
constexpr int kB   = 8;
constexpr int kL   = 4096;
constexpr int kDM  = 512;
constexpr int kDI  = 1024;
constexpr int kDXZ = 2048;
constexpr int kN   = 16;
constexpr int kR   = 32;
constexpr int kDBC = 64;
constexpr int kFF  = 2048;
constexpr int kT   = kB * kL;

// half-unit offsets into fp16 weight scratch
constexpr size_t oInF  = 0;
constexpr size_t oInB  = oInF  + 2048 * 512;
constexpr size_t oXpF  = oInB  + 2048 * 512;
constexpr size_t oXpB  = oXpF  + 64 * 1024;
constexpr size_t oDtF  = oXpB  + 64 * 1024;
constexpr size_t oDtB  = oDtF  + 1024 * 32;
constexpr size_t oOutF = oDtB  + 1024 * 32;
constexpr size_t oOutB = oOutF + 512 * 1024;
constexpr size_t oF1   = oOutB + 512 * 1024;
constexpr size_t oF2   = oF1   + 2048 * 512;
constexpr size_t kWH   = oF2   + 512 * 2048;
}

// fp16 activations (GEMM-feeding)
__device__ __half g_xh  [(size_t)kT * kDM];   // x in fp16
__device__ __half g_xzh [(size_t)kT * kDXZ];  // in_proj out; also ffn hidden
__device__ __half g_xch [(size_t)kT * kDI];
__device__ __half g_dbch[(size_t)kT * kDBC];
__device__ __half g_dth [(size_t)kT * kDI];
__device__ __half g_yh  [(size_t)kT * kDI];
__device__ __half g_hh  [(size_t)kT * kDM];
__device__ __half g_wh  [kWH];                // fp16 weights
// fp32 (output-critical)
__device__ float  g_mf  [(size_t)kT * kDM];   // also ff out
__device__ float  g_mb  [(size_t)kT * kDM];
__device__ float  g_h   [(size_t)kT * kDM];

__device__ __forceinline__ void mma_f16(float* d,
    uint32_t a0, uint32_t a1, uint32_t a2, uint32_t a3,
    uint32_t b0, uint32_t b1)
{
  asm volatile(
    "mma.sync.aligned.m16n8k16.row.col.f32.f16.f16.f32 "
    "{%0,%1,%2,%3}, {%4,%5,%6,%7}, {%8,%9}, {%0,%1,%2,%3};\n"
    : "+f"(d[0]), "+f"(d[1]), "+f"(d[2]), "+f"(d[3])
    : "r"(a0), "r"(a1), "r"(a2), "r"(a3), "r"(b0), "r"(b1));
}
__device__ __forceinline__ void ldsm4(uint32_t* r, uint32_t addr) {
  asm volatile(
    "ldmatrix.sync.aligned.m8n8.x4.shared.b16 {%0,%1,%2,%3}, [%4];"
    : "=r"(r[0]), "=r"(r[1]), "=r"(r[2]), "=r"(r[3]) : "r"(addr));
}
__device__ __forceinline__ void ldsm2(uint32_t& r0, uint32_t& r1, uint32_t addr) {
  asm volatile(
    "ldmatrix.sync.aligned.m8n8.x2.shared.b16 {%0,%1}, [%2];"
    : "=r"(r0), "=r"(r1) : "r"(addr));
}
__device__ __forceinline__ uint32_t pack_h2(float a, float b) {
  __half2 h = __floats2half2_rn(a, b);
  return *reinterpret_cast<uint32_t*>(&h);
}

// float4 -> 4x fp16 conversion (one-time passes)
__global__ void f2h_k(const float4* __restrict__ s, uint2* __restrict__ d, int n4) {
  int i = blockIdx.x * blockDim.x + threadIdx.x;
  if (i < n4) {
    float4 v = s[i];
    uint2 o = { pack_h2(v.x, v.y), pack_h2(v.z, v.w) };
    d[i] = o;
  }
}

// ---------------------------------------------------------------------------
// C[M,N] = A[M,K](fp16, row stride lda) * W[N,K]^T(fp16) (+ epilogue)
// EPI: 0 none, 1 softplus(+bias), 2 gelu(+bias), 3 +bias
// OUTH: 1 = write fp16 C, 0 = write fp32 C.
// 128 threads = 4 warps (2x2), warp tile 64x32, BK=32, smem ST2=40 halves.
// Requires M%128==0, N%64==0, K%32==0.
// ---------------------------------------------------------------------------
template<int EPI, int OUTH>
__global__ void __launch_bounds__(128, 3) gemm_h(
    const __half* __restrict__ A, int lda,
    const __half* __restrict__ W,
    const float* __restrict__ bias,
    void* __restrict__ Cp, int M, int N, int K)
{
  constexpr int BM = 128, BN = 64, BK = 32, ST2 = 40;
  __shared__ __half As[BM * ST2];
  __shared__ __half Ws[BN * ST2];

  const int tid  = threadIdx.x;
  const int lane = tid & 31;
  const int wid  = tid >> 5;
  const int wm   = (wid & 1) * 64;
  const int wn   = (wid >> 1) * 32;
  const size_t bm = (size_t)blockIdx.y * BM;
  const int bn   = blockIdx.x * BN;
  const int g4   = lane >> 2;
  const int t4   = lane & 3;

  float acc[4][4][4];
  #pragma unroll
  for (int i = 0; i < 4; i++)
    #pragma unroll
    for (int j = 0; j < 4; j++)
      #pragma unroll
      for (int c = 0; c < 4; c++) acc[i][j][c] = 0.f;

  // Loaders: fp16 tiles. A: 128x32 halves = 512 uint4 -> 4/thread.
  //          W: 64x32 halves = 256 uint4 -> 2/thread.
  const int ldR = tid >> 2;            // 0..31
  const int ldC = (tid & 3) * 8;       // half col 0,8,16,24

  uint4 aR[4], wR[2];

  auto ldg_tiles = [&](int k0) {
    #pragma unroll
    for (int i = 0; i < 4; i++) {
      int r = ldR + 32 * i;
      aR[i] = *reinterpret_cast<const uint4*>(&A[(bm + r) * (size_t)lda + k0 + ldC]);
    }
    #pragma unroll
    for (int i = 0; i < 2; i++) {
      int r = ldR + 32 * i;
      wR[i] = *reinterpret_cast<const uint4*>(&W[(size_t)(bn + r) * K + k0 + ldC]);
    }
  };
  auto sts_tiles = [&]() {
    #pragma unroll
    for (int i = 0; i < 4; i++) {
      int r = ldR + 32 * i;
      *reinterpret_cast<uint4*>(&As[r * ST2 + ldC]) = aR[i];
    }
    #pragma unroll
    for (int i = 0; i < 2; i++) {
      int r = ldR + 32 * i;
      *reinterpret_cast<uint4*>(&Ws[r * ST2 + ldC]) = wR[i];
    }
  };

  // ldmatrix per-lane addresses (identical layout to R9)
  const int mrow = lane & 7;
  const int mat  = lane >> 3;
  uint32_t aAddr[4], bAddr[4];
  {
    const uint32_t asB = (uint32_t)__cvta_generic_to_shared(As);
    const uint32_t wsB = (uint32_t)__cvta_generic_to_shared(Ws);
    #pragma unroll
    for (int mi = 0; mi < 4; mi++)
      aAddr[mi] = asB + (uint32_t)(((wm + mi * 16 + (mat & 1) * 8 + mrow) * ST2
                                    + (mat >> 1) * 8) * 2);
    #pragma unroll
    for (int nj = 0; nj < 4; nj++)
      bAddr[nj] = wsB + (uint32_t)(((wn + nj * 8 + mrow) * ST2
                                    + (mat & 1) * 8) * 2);
  }

  ldg_tiles(0);
  sts_tiles();
  __syncthreads();

  for (int k0 = 0; k0 < K; k0 += BK) {
    const bool more = (k0 + BK) < K;
    if (more) ldg_tiles(k0 + BK);

    #pragma unroll
    for (int kk = 0; kk < 2; kk++) {
      uint32_t a[4][4];
      uint32_t b[4][2];
      #pragma unroll
      for (int mi = 0; mi < 4; mi++)
        ldsm4(a[mi], aAddr[mi] + (uint32_t)(kk * 32));
      #pragma unroll
      for (int nj = 0; nj < 4; nj++)
        ldsm2(b[nj][0], b[nj][1], bAddr[nj] + (uint32_t)(kk * 32));
      #pragma unroll
      for (int mi = 0; mi < 4; mi++)
        #pragma unroll
        for (int nj = 0; nj < 4; nj++)
          mma_f16(acc[mi][nj], a[mi][0], a[mi][1], a[mi][2], a[mi][3],
                  b[nj][0], b[nj][1]);
    }
    __syncthreads();
    if (more) {
      sts_tiles();
      __syncthreads();
    }
  }

  // Epilogue
  #pragma unroll
  for (int mi = 0; mi < 4; mi++) {
    #pragma unroll
    for (int nj = 0; nj < 4; nj++) {
      size_t r0 = bm + wm + mi * 16 + g4;
      int c0 = bn + wn + nj * 8 + 2 * t4;
      #pragma unroll
      for (int half = 0; half < 2; half++) {
        size_t row = r0 + half * 8;
        float vx = acc[mi][nj][half * 2 + 0];
        float vy = acc[mi][nj][half * 2 + 1];
        if (EPI == 1) {
          vx += __ldg(&bias[c0]);     vy += __ldg(&bias[c0 + 1]);
          vx = fmaxf(vx, 0.f) + log1pf(__expf(-fabsf(vx)));
          vy = fmaxf(vy, 0.f) + log1pf(__expf(-fabsf(vy)));
        } else if (EPI == 2) {
          vx += __ldg(&bias[c0]);     vy += __ldg(&bias[c0 + 1]);
          float tx = tanhf(0.7978845608028654f * (vx + 0.044715f * vx * vx * vx));
          float ty = tanhf(0.7978845608028654f * (vy + 0.044715f * vy * vy * vy));
          vx = 0.5f * vx * (1.f + tx);
          vy = 0.5f * vy * (1.f + ty);
        } else if (EPI == 3) {
          vx += __ldg(&bias[c0]);     vy += __ldg(&bias[c0 + 1]);
        }
        if (OUTH) {
          *reinterpret_cast<uint32_t*>(&((__half*)Cp)[row * (size_t)N + c0]) =
              pack_h2(vx, vy);
        } else {
          float2 v2 = { vx, vy };
          *reinterpret_cast<float2*>(&((float*)Cp)[row * (size_t)N + c0]) = v2;
        }
      }
    }
  }
}

// ---------------------------------------------------------------------------
// Depthwise causal conv (k=4) + bias + silu on fp16; dir=+1 fwd, -1 bwd.
// ---------------------------------------------------------------------------
__global__ void conv_silu_k(const float* __restrict__ cw,
                            const float* __restrict__ cb, int dir)
{
  int i = blockIdx.x * blockDim.x + threadIdx.x;
  int d = i & (kDI - 1);
  int tok = i >> 10;
  int pos = tok & (kL - 1);
  float acc = __ldg(&cb[d]);
  #pragma unroll
  for (int j = 0; j < 4; j++) {
    int o = (dir > 0) ? (j - 3) : (3 - j);
    int p = pos + o;
    if (p >= 0 && p < kL)
      acc = fmaf(__ldg(&cw[d * 4 + j]),
                 __half2float(g_xzh[(size_t)(tok + o) * kDXZ + d]), acc);
  }
  g_xch[i] = __float2half(acc / (1.f + __expf(-acc)));
}

// ---------------------------------------------------------------------------
// Selective scan on fp16 inputs, warp = 2 channels (16 state lanes each).
// ---------------------------------------------------------------------------
__global__ void scan_k(const float* __restrict__ A_log,
                       const float* __restrict__ Dp, int dir)
{
  int gw   = (blockIdx.x * blockDim.x + threadIdx.x) >> 5;
  int lane = threadIdx.x & 31;
  int half = lane >> 4;
  int n    = lane & 15;
  int ch   = gw * 2 + half;
  int b    = ch >> 10;
  int d    = ch & (kDI - 1);

  float A  = -__expf(__ldg(&A_log[d * kN + n]));
  float Dv = __ldg(&Dp[d]);
  float h  = 0.f;
  const size_t tokbase = (size_t)b * kL;

  for (int u = 0; u < kL; ++u) {
    int pos = (dir > 0) ? u : (kL - 1 - u);
    size_t tok = tokbase + pos;
    float dtv = __half2float(g_dth [tok * kDI  + d]);
    float xv  = __half2float(g_xch [tok * kDI  + d]);
    float Bv  = __half2float(g_dbch[tok * kDBC + kR + n]);
    float Cv  = __half2float(g_dbch[tok * kDBC + kR + kN + n]);
    float a   = __expf(dtv * A);
    h = fmaf(a, h, dtv * xv * Bv);
    float p = h * Cv;
    p += __shfl_xor_sync(0xffffffffu, p, 1);
    p += __shfl_xor_sync(0xffffffffu, p, 2);
    p += __shfl_xor_sync(0xffffffffu, p, 4);
    p += __shfl_xor_sync(0xffffffffu, p, 8);
    if (n == 0) {
      float zv = __half2float(g_xzh[tok * kDXZ + kDI + d]);
      float sz = zv / (1.f + __expf(-zv));
      g_yh[tok * kDI + d] = __float2half((p + xv * Dv) * sz);
    }
  }
}

// ---------------------------------------------------------------------------
// LayerNorms
// ---------------------------------------------------------------------------
__device__ __forceinline__ float warp_sum(float v) {
  v += __shfl_xor_sync(0xffffffffu, v, 16);
  v += __shfl_xor_sync(0xffffffffu, v, 8);
  v += __shfl_xor_sync(0xffffffffu, v, 4);
  v += __shfl_xor_sync(0xffffffffu, v, 2);
  v += __shfl_xor_sync(0xffffffffu, v, 1);
  return v;
}

// h = 0.5*(LN(x+mf)+LN(x+mb)); writes fp32 g_h (final LN) + fp16 g_hh (ffn1).
__global__ void ln_combine_k(const float* __restrict__ x,
    const float* __restrict__ gf, const float* __restrict__ bf,
    const float* __restrict__ gb, const float* __restrict__ bb)
{
  int row  = blockIdx.x * (blockDim.x >> 5) + (threadIdx.x >> 5);
  int lane = threadIdx.x & 31;
  const float* xr = x    + (size_t)row * kDM;
  const float* fr = g_mf + (size_t)row * kDM;
  const float* br = g_mb + (size_t)row * kDM;

  float u[16], v[16];
  float su = 0.f, sv = 0.f;
  #pragma unroll
  for (int k = 0; k < 4; k++) {
    int idx = (k * 32 + lane) * 4;
    float4 a  = *reinterpret_cast<const float4*>(xr + idx);
    float4 m1 = *reinterpret_cast<const float4*>(fr + idx);
    float4 m2 = *reinterpret_cast<const float4*>(br + idx);
    u[k*4+0]=a.x+m1.x; u[k*4+1]=a.y+m1.y; u[k*4+2]=a.z+m1.z; u[k*4+3]=a.w+m1.w;
    v[k*4+0]=a.x+m2.x; v[k*4+1]=a.y+m2.y; v[k*4+2]=a.z+m2.z; v[k*4+3]=a.w+m2.w;
    #pragma unroll
    for (int c = 0; c < 4; c++) { su += u[k*4+c]; sv += v[k*4+c]; }
  }
  float muU = warp_sum(su) * (1.f / kDM);
  float muV = warp_sum(sv) * (1.f / kDM);
  float qu = 0.f, qv = 0.f;
  #pragma unroll
  for (int c = 0; c < 16; c++) {
    float du = u[c] - muU, dv = v[c] - muV;
    qu += du * du; qv += dv * dv;
  }
  float rsU = rsqrtf(warp_sum(qu) * (1.f / kDM) + 1e-5f);
  float rsV = rsqrtf(warp_sum(qv) * (1.f / kDM) + 1e-5f);

  float* hr  = g_h  + (size_t)row * kDM;
  __half* hh = g_hh + (size_t)row * kDM;
  #pragma unroll
  for (int k = 0; k < 4; k++) {
    int idx = (k * 32 + lane) * 4;
    float4 o;
    #pragma unroll
    for (int c = 0; c < 4; c++) {
      int f = idx + c;
      float a = (u[k*4+c] - muU) * rsU * __ldg(&gf[f]) + __ldg(&bf[f]);
      float bvv = (v[k*4+c] - muV) * rsV * __ldg(&gb[f]) + __ldg(&bb[f]);
      ((float*)&o)[c] = 0.5f * (a + bvv);
    }
    *reinterpret_cast<float4*>(hr + idx) = o;
    uint2 oh = { pack_h2(o.x, o.y), pack_h2(o.z, o.w) };
    *reinterpret_cast<uint2*>(hh + idx) = oh;
  }
}

__global__ void ln_final_k(const float* __restrict__ ff,
    const float* __restrict__ g, const float* __restrict__ bia,
    float* __restrict__ out)
{
  int row  = blockIdx.x * (blockDim.x >> 5) + (threadIdx.x >> 5);
  int lane = threadIdx.x & 31;
  const float* hr = g_h + (size_t)row * kDM;
  const float* fr = ff  + (size_t)row * kDM;

  float u[16];
  float su = 0.f;
  #pragma unroll
  for (int k = 0; k < 4; k++) {
    int idx = (k * 32 + lane) * 4;
    float4 a  = *reinterpret_cast<const float4*>(hr + idx);
    float4 m1 = *reinterpret_cast<const float4*>(fr + idx);
    u[k*4+0]=a.x+m1.x; u[k*4+1]=a.y+m1.y; u[k*4+2]=a.z+m1.z; u[k*4+3]=a.w+m1.w;
    #pragma unroll
    for (int c = 0; c < 4; c++) su += u[k*4+c];
  }
  float mu = warp_sum(su) * (1.f / kDM);
  float q = 0.f;
  #pragma unroll
  for (int c = 0; c < 16; c++) { float d = u[c] - mu; q += d * d; }
  float rs = rsqrtf(warp_sum(q) * (1.f / kDM) + 1e-5f);

  float* orow = out + (size_t)row * kDM;
  #pragma unroll
  for (int k = 0; k < 4; k++) {
    int idx = (k * 32 + lane) * 4;
    float4 o;
    #pragma unroll
    for (int c = 0; c < 4; c++) {
      int f = idx + c;
      ((float*)&o)[c] = (u[k*4+c] - mu) * rs * __ldg(&g[f]) + __ldg(&bia[f]);
    }
    *reinterpret_cast<float4*>(orow + idx) = o;
  }
}

// ---------------------------------------------------------------------------
// Launch
// ---------------------------------------------------------------------------
extern "C" void kernel_launch(void* const* d_in, const int* in_sizes, int n_in,
                              void* d_out, int out_size)
{
  const float* x = (const float*)d_in[0];
  const float* const* Pf = (const float* const*)&d_in[1];
  const float* const* Pb = (const float* const*)&d_in[10];
  const float* ln_f_g  = (const float*)d_in[19];
  const float* ln_f_b  = (const float*)d_in[20];
  const float* ln_b_g  = (const float*)d_in[21];
  const float* ln_b_b  = (const float*)d_in[22];
  const float* ln_ff_g = (const float*)d_in[23];
  const float* ln_ff_b = (const float*)d_in[24];
  const float* ffn_w1  = (const float*)d_in[25];
  const float* ffn_b1  = (const float*)d_in[26];
  const float* ffn_w2  = (const float*)d_in[27];
  const float* ffn_b2  = (const float*)d_in[28];
  float* out = (float*)d_out;

  void *p_xh, *p_xzh, *p_xch, *p_dbch, *p_dth, *p_yh, *p_hh, *p_wh;
  void *p_mf, *p_mb, *p_h;
  cudaGetSymbolAddress(&p_xh,   g_xh);
  cudaGetSymbolAddress(&p_xzh,  g_xzh);
  cudaGetSymbolAddress(&p_xch,  g_xch);
  cudaGetSymbolAddress(&p_dbch, g_dbch);
  cudaGetSymbolAddress(&p_dth,  g_dth);
  cudaGetSymbolAddress(&p_yh,   g_yh);
  cudaGetSymbolAddress(&p_hh,   g_hh);
  cudaGetSymbolAddress(&p_wh,   g_wh);
  cudaGetSymbolAddress(&p_mf,   g_mf);
  cudaGetSymbolAddress(&p_mb,   g_mb);
  cudaGetSymbolAddress(&p_h,    g_h);
  __half* wh = (__half*)p_wh;
  __half* xh = (__half*)p_xh;

  const dim3 blk(128);
  const int rowsY = kT / 128;   // 256

  // One-time fp32 -> fp16 conversions (x + all weights)
  auto cvt = [&](const float* src, __half* dst, size_t n) {
    int n4 = (int)(n / 4);
    f2h_k<<<(n4 + 255) / 256, dim3(256)>>>(
        (const float4*)src, (uint2*)dst, n4);
  };
  cvt(x, xh, (size_t)kT * kDM);
  cvt(Pf[0], wh + oInF,  2048 * 512);
  cvt(Pb[0], wh + oInB,  2048 * 512);
  cvt(Pf[3], wh + oXpF,  64 * 1024);
  cvt(Pb[3], wh + oXpB,  64 * 1024);
  cvt(Pf[4], wh + oDtF,  1024 * 32);
  cvt(Pb[4], wh + oDtB,  1024 * 32);
  cvt(Pf[8], wh + oOutF, 512 * 1024);
  cvt(Pb[8], wh + oOutB, 512 * 1024);
  cvt(ffn_w1, wh + oF1,  2048 * 512);
  cvt(ffn_w2, wh + oF2,  512 * 2048);

  auto run_block = [&](const float* const* P, float* mout, int dir,
                       const __half* w_in, const __half* w_xp,
                       const __half* w_dt, const __half* w_out) {
    gemm_h<0,1><<<dim3(kDXZ / 64, rowsY), blk>>>(xh, kDM, w_in, nullptr,
                                                 p_xzh, kT, kDXZ, kDM);
    conv_silu_k<<<(kT * kDI) / 256, dim3(256)>>>(P[1], P[2], dir);
    gemm_h<0,1><<<dim3(kDBC / 64, rowsY), blk>>>((const __half*)p_xch, kDI, w_xp,
                                                 nullptr, p_dbch, kT, kDBC, kDI);
    gemm_h<1,1><<<dim3(kDI / 64, rowsY), blk>>>((const __half*)p_dbch, kDBC, w_dt,
                                                P[5], p_dth, kT, kDI, kR);
    scan_k<<<512, dim3(256)>>>(P[6], P[7], dir);
    gemm_h<0,0><<<dim3(kDM / 64, rowsY), blk>>>((const __half*)p_yh, kDI, w_out,
                                                nullptr, mout, kT, kDM, kDI);
  };

  run_block(Pf, (float*)p_mf, +1, wh + oInF, wh + oXpF, wh + oDtF, wh + oOutF);
  run_block(Pb, (float*)p_mb, -1, wh + oInB, wh + oXpB, wh + oDtB, wh + oOutB);

  ln_combine_k<<<kT / 8, dim3(256)>>>(x, ln_f_g, ln_f_b, ln_b_g, ln_b_b);

  // FFN: hidden (fp16, reuse g_xzh) then ff (fp32, reuse g_mf)
  gemm_h<2,1><<<dim3(kFF / 64, rowsY), blk>>>((const __half*)p_hh, kDM, wh + oF1,
                                              ffn_b1, p_xzh, kT, kFF, kDM);
  gemm_h<3,0><<<dim3(kDM / 64, rowsY), blk>>>((const __half*)p_xzh, kFF, wh + oF2,
                                              ffn_b2, p_mf, kT, kDM, kFF);

  ln_final_k<<<kT / 8, dim3(256)>>>((const float*)p_mf, ln_ff_g, ln_ff_b, out);
}

// round 13
// speedup vs baseline: 1.1514x; 1.0653x over previous
#include <cuda_runtime.h>
#include <cuda_fp16.h>
#include <cstdint>

// ---------------------------------------------------------------------------
// BiMambaLayer on GB300 — Round 11: R10 (fp16 end-to-end) + 3-stage cp.async
// pipelined GEMM (depth-2 prefetch, one barrier per K-tile) + fused cvt pass.
// ---------------------------------------------------------------------------

namespace {
constexpr int kB   = 8;
constexpr int kL   = 4096;
constexpr int kDM  = 512;
constexpr int kDI  = 1024;
constexpr int kDXZ = 2048;
constexpr int kN   = 16;
constexpr int kR   = 32;
constexpr int kDBC = 64;
constexpr int kFF  = 2048;
constexpr int kT   = kB * kL;

constexpr size_t oInF  = 0;
constexpr size_t oInB  = oInF  + 2048 * 512;
constexpr size_t oXpF  = oInB  + 2048 * 512;
constexpr size_t oXpB  = oXpF  + 64 * 1024;
constexpr size_t oDtF  = oXpB  + 64 * 1024;
constexpr size_t oDtB  = oDtF  + 1024 * 32;
constexpr size_t oOutF = oDtB  + 1024 * 32;
constexpr size_t oOutB = oOutF + 512 * 1024;
constexpr size_t oF1   = oOutB + 512 * 1024;
constexpr size_t oF2   = oF1   + 2048 * 512;
constexpr size_t kWH   = oF2   + 512 * 2048;
}

// fp16 activations (GEMM-feeding)
__device__ __half g_xh  [(size_t)kT * kDM];
__device__ __half g_xzh [(size_t)kT * kDXZ];
__device__ __half g_xch [(size_t)kT * kDI];
__device__ __half g_dbch[(size_t)kT * kDBC];
__device__ __half g_dth [(size_t)kT * kDI];
__device__ __half g_yh  [(size_t)kT * kDI];
__device__ __half g_hh  [(size_t)kT * kDM];
__device__ __half g_wh  [kWH];
// fp32 (output-critical)
__device__ float  g_mf  [(size_t)kT * kDM];
__device__ float  g_mb  [(size_t)kT * kDM];
__device__ float  g_h   [(size_t)kT * kDM];

__device__ __forceinline__ void mma_f16(float* d,
    uint32_t a0, uint32_t a1, uint32_t a2, uint32_t a3,
    uint32_t b0, uint32_t b1)
{
  asm volatile(
    "mma.sync.aligned.m16n8k16.row.col.f32.f16.f16.f32 "
    "{%0,%1,%2,%3}, {%4,%5,%6,%7}, {%8,%9}, {%0,%1,%2,%3};\n"
    : "+f"(d[0]), "+f"(d[1]), "+f"(d[2]), "+f"(d[3])
    : "r"(a0), "r"(a1), "r"(a2), "r"(a3), "r"(b0), "r"(b1));
}
__device__ __forceinline__ void ldsm4(uint32_t* r, uint32_t addr) {
  asm volatile(
    "ldmatrix.sync.aligned.m8n8.x4.shared.b16 {%0,%1,%2,%3}, [%4];"
    : "=r"(r[0]), "=r"(r[1]), "=r"(r[2]), "=r"(r[3]) : "r"(addr));
}
__device__ __forceinline__ void ldsm2(uint32_t& r0, uint32_t& r1, uint32_t addr) {
  asm volatile(
    "ldmatrix.sync.aligned.m8n8.x2.shared.b16 {%0,%1}, [%2];"
    : "=r"(r0), "=r"(r1) : "r"(addr));
}
__device__ __forceinline__ uint32_t pack_h2(float a, float b) {
  __half2 h = __floats2half2_rn(a, b);
  return *reinterpret_cast<uint32_t*>(&h);
}
__device__ __forceinline__ void cpa16(uint32_t s, const void* g) {
  asm volatile("cp.async.cg.shared.global [%0], [%1], 16;" :: "r"(s), "l"(g));
}
__device__ __forceinline__ void cpa_commit() {
  asm volatile("cp.async.commit_group;" ::: "memory");
}
template<int NN>
__device__ __forceinline__ void cpa_wait() {
  asm volatile("cp.async.wait_group %0;" :: "n"(NN) : "memory");
}

// Fused fp32 -> fp16 conversion over up to 12 segments (one launch).
struct CvtJobs {
  const float4* src[12];
  uint2* dst[12];
  int n4[12];
  int njobs;
};
__global__ void f2h_all_k(CvtJobs jobs) {
  int j = blockIdx.y;
  if (j >= jobs.njobs) return;
  const float4* s = jobs.src[j];
  uint2* d = jobs.dst[j];
  int n4 = jobs.n4[j];
  for (int i = blockIdx.x * blockDim.x + threadIdx.x; i < n4;
       i += gridDim.x * blockDim.x) {
    float4 v = s[i];
    uint2 o = { pack_h2(v.x, v.y), pack_h2(v.z, v.w) };
    d[i] = o;
  }
}

// ---------------------------------------------------------------------------
// C[M,N] = A[M,K](fp16, lda) * W[N,K]^T(fp16) (+ epilogue)
// 3-stage cp.async pipeline, BK=32, one __syncthreads per K-tile.
// EPI: 0 none, 1 softplus(+bias), 2 gelu(+bias), 3 +bias; OUTH: fp16 C.
// 128 threads = 4 warps (2x2), warp tile 64x32. M%128==0, N%64==0, K%32==0.
// ---------------------------------------------------------------------------
template<int EPI, int OUTH>
__global__ void __launch_bounds__(128, 3) gemm_h(
    const __half* __restrict__ A, int lda,
    const __half* __restrict__ W,
    const float* __restrict__ bias,
    void* __restrict__ Cp, int M, int N, int K)
{
  constexpr int BM = 128, BN = 64, BK = 32, ST2 = 40, STG = 3;
  constexpr int STAGE_H = (BM + BN) * ST2;          // halves per stage (7680)
  constexpr uint32_t STAGE_B = STAGE_H * 2;         // bytes per stage (15360)
  __shared__ __half Sm[STG * STAGE_H];              // 46080 B

  const int tid  = threadIdx.x;
  const int lane = tid & 31;
  const int wid  = tid >> 5;
  const int wm   = (wid & 1) * 64;
  const int wn   = (wid >> 1) * 32;
  const size_t bm = (size_t)blockIdx.y * BM;
  const int bn   = blockIdx.x * BN;
  const int g4   = lane >> 2;
  const int t4   = lane & 3;
  const int ntiles = K / BK;

  float acc[4][4][4];
  #pragma unroll
  for (int i = 0; i < 4; i++)
    #pragma unroll
    for (int j = 0; j < 4; j++)
      #pragma unroll
      for (int c = 0; c < 4; c++) acc[i][j][c] = 0.f;

  // cp.async geometry: A 128x32 halves = 512x16B -> 4/thread; W -> 2/thread.
  const int ldR = tid >> 2;            // 0..31
  const int ldC = (tid & 3) * 8;       // half col 0,8,16,24

  const __half* aG[4];
  const __half* wG[2];
  uint32_t aDst[4], wDst[2];
  const uint32_t smBase = (uint32_t)__cvta_generic_to_shared(Sm);
  #pragma unroll
  for (int i = 0; i < 4; i++) {
    int r = ldR + 32 * i;
    aG[i]   = &A[(bm + r) * (size_t)lda + ldC];
    aDst[i] = smBase + (uint32_t)((r * ST2 + ldC) * 2);
  }
  #pragma unroll
  for (int i = 0; i < 2; i++) {
    int r = ldR + 32 * i;
    wG[i]   = &W[(size_t)(bn + r) * K + ldC];
    wDst[i] = smBase + (uint32_t)(((BM + r) * ST2 + ldC) * 2);
  }

  auto issue = [&](int stage) {
    const uint32_t so = (uint32_t)stage * STAGE_B;
    #pragma unroll
    for (int i = 0; i < 4; i++) { cpa16(aDst[i] + so, aG[i]); aG[i] += BK; }
    #pragma unroll
    for (int i = 0; i < 2; i++) { cpa16(wDst[i] + so, wG[i]); wG[i] += BK; }
    cpa_commit();
  };

  // ldmatrix per-lane base addresses (stage 0)
  const int mrow = lane & 7;
  const int mat  = lane >> 3;
  uint32_t aAddr[4], bAddr[4];
  #pragma unroll
  for (int mi = 0; mi < 4; mi++)
    aAddr[mi] = smBase + (uint32_t)(((wm + mi * 16 + (mat & 1) * 8 + mrow) * ST2
                                     + (mat >> 1) * 8) * 2);
  #pragma unroll
  for (int nj = 0; nj < 4; nj++)
    bAddr[nj] = smBase + (uint32_t)(((BM + wn + nj * 8 + mrow) * ST2
                                     + (mat & 1) * 8) * 2);

  // Prologue: keep group count uniform with empty commits.
  if (0 < ntiles) issue(0); else cpa_commit();
  if (1 < ntiles) issue(1); else cpa_commit();

  int stage = 0;
  for (int t = 0; t < ntiles; t++) {
    cpa_wait<1>();           // stage t landed (groups are FIFO; count uniform)
    __syncthreads();         // visibility + all warps done computing t-1

    if (t + 2 < ntiles) issue((stage + 2) % STG); else cpa_commit();

    const uint32_t so = (uint32_t)stage * STAGE_B;
    #pragma unroll
    for (int kk = 0; kk < 2; kk++) {
      uint32_t a[4][4];
      uint32_t b[4][2];
      #pragma unroll
      for (int mi = 0; mi < 4; mi++)
        ldsm4(a[mi], aAddr[mi] + so + (uint32_t)(kk * 32));
      #pragma unroll
      for (int nj = 0; nj < 4; nj++)
        ldsm2(b[nj][0], b[nj][1], bAddr[nj] + so + (uint32_t)(kk * 32));
      #pragma unroll
      for (int mi = 0; mi < 4; mi++)
        #pragma unroll
        for (int nj = 0; nj < 4; nj++)
          mma_f16(acc[mi][nj], a[mi][0], a[mi][1], a[mi][2], a[mi][3],
                  b[nj][0], b[nj][1]);
    }
    stage = (stage + 1 == STG) ? 0 : stage + 1;
  }

  // Epilogue (R10-identical)
  #pragma unroll
  for (int mi = 0; mi < 4; mi++) {
    #pragma unroll
    for (int nj = 0; nj < 4; nj++) {
      size_t r0 = bm + wm + mi * 16 + g4;
      int c0 = bn + wn + nj * 8 + 2 * t4;
      #pragma unroll
      for (int half = 0; half < 2; half++) {
        size_t row = r0 + half * 8;
        float vx = acc[mi][nj][half * 2 + 0];
        float vy = acc[mi][nj][half * 2 + 1];
        if (EPI == 1) {
          vx += __ldg(&bias[c0]);     vy += __ldg(&bias[c0 + 1]);
          vx = fmaxf(vx, 0.f) + log1pf(__expf(-fabsf(vx)));
          vy = fmaxf(vy, 0.f) + log1pf(__expf(-fabsf(vy)));
        } else if (EPI == 2) {
          vx += __ldg(&bias[c0]);     vy += __ldg(&bias[c0 + 1]);
          float tx = tanhf(0.7978845608028654f * (vx + 0.044715f * vx * vx * vx));
          float ty = tanhf(0.7978845608028654f * (vy + 0.044715f * vy * vy * vy));
          vx = 0.5f * vx * (1.f + tx);
          vy = 0.5f * vy * (1.f + ty);
        } else if (EPI == 3) {
          vx += __ldg(&bias[c0]);     vy += __ldg(&bias[c0 + 1]);
        }
        if (OUTH) {
          *reinterpret_cast<uint32_t*>(&((__half*)Cp)[row * (size_t)N + c0]) =
              pack_h2(vx, vy);
        } else {
          float2 v2 = { vx, vy };
          *reinterpret_cast<float2*>(&((float*)Cp)[row * (size_t)N + c0]) = v2;
        }
      }
    }
  }
}

// ---------------------------------------------------------------------------
// Depthwise causal conv (k=4) + bias + silu on fp16; dir=+1 fwd, -1 bwd.
// ---------------------------------------------------------------------------
__global__ void conv_silu_k(const float* __restrict__ cw,
                            const float* __restrict__ cb, int dir)
{
  int i = blockIdx.x * blockDim.x + threadIdx.x;
  int d = i & (kDI - 1);
  int tok = i >> 10;
  int pos = tok & (kL - 1);
  float acc = __ldg(&cb[d]);
  #pragma unroll
  for (int j = 0; j < 4; j++) {
    int o = (dir > 0) ? (j - 3) : (3 - j);
    int p = pos + o;
    if (p >= 0 && p < kL)
      acc = fmaf(__ldg(&cw[d * 4 + j]),
                 __half2float(g_xzh[(size_t)(tok + o) * kDXZ + d]), acc);
  }
  g_xch[i] = __float2half(acc / (1.f + __expf(-acc)));
}

// ---------------------------------------------------------------------------
// Selective scan on fp16 inputs, warp = 2 channels (16 state lanes each).
// ---------------------------------------------------------------------------
__global__ void scan_k(const float* __restrict__ A_log,
                       const float* __restrict__ Dp, int dir)
{
  int gw   = (blockIdx.x * blockDim.x + threadIdx.x) >> 5;
  int lane = threadIdx.x & 31;
  int half = lane >> 4;
  int n    = lane & 15;
  int ch   = gw * 2 + half;
  int b    = ch >> 10;
  int d    = ch & (kDI - 1);

  float A  = -__expf(__ldg(&A_log[d * kN + n]));
  float Dv = __ldg(&Dp[d]);
  float h  = 0.f;
  const size_t tokbase = (size_t)b * kL;

  for (int u = 0; u < kL; ++u) {
    int pos = (dir > 0) ? u : (kL - 1 - u);
    size_t tok = tokbase + pos;
    float dtv = __half2float(g_dth [tok * kDI  + d]);
    float xv  = __half2float(g_xch [tok * kDI  + d]);
    float Bv  = __half2float(g_dbch[tok * kDBC + kR + n]);
    float Cv  = __half2float(g_dbch[tok * kDBC + kR + kN + n]);
    float a   = __expf(dtv * A);
    h = fmaf(a, h, dtv * xv * Bv);
    float p = h * Cv;
    p += __shfl_xor_sync(0xffffffffu, p, 1);
    p += __shfl_xor_sync(0xffffffffu, p, 2);
    p += __shfl_xor_sync(0xffffffffu, p, 4);
    p += __shfl_xor_sync(0xffffffffu, p, 8);
    if (n == 0) {
      float zv = __half2float(g_xzh[tok * kDXZ + kDI + d]);
      float sz = zv / (1.f + __expf(-zv));
      g_yh[tok * kDI + d] = __float2half((p + xv * Dv) * sz);
    }
  }
}

// ---------------------------------------------------------------------------
// LayerNorms
// ---------------------------------------------------------------------------
__device__ __forceinline__ float warp_sum(float v) {
  v += __shfl_xor_sync(0xffffffffu, v, 16);
  v += __shfl_xor_sync(0xffffffffu, v, 8);
  v += __shfl_xor_sync(0xffffffffu, v, 4);
  v += __shfl_xor_sync(0xffffffffu, v, 2);
  v += __shfl_xor_sync(0xffffffffu, v, 1);
  return v;
}

__global__ void ln_combine_k(const float* __restrict__ x,
    const float* __restrict__ gf, const float* __restrict__ bf,
    const float* __restrict__ gb, const float* __restrict__ bb)
{
  int row  = blockIdx.x * (blockDim.x >> 5) + (threadIdx.x >> 5);
  int lane = threadIdx.x & 31;
  const float* xr = x    + (size_t)row * kDM;
  const float* fr = g_mf + (size_t)row * kDM;
  const float* br = g_mb + (size_t)row * kDM;

  float u[16], v[16];
  float su = 0.f, sv = 0.f;
  #pragma unroll
  for (int k = 0; k < 4; k++) {
    int idx = (k * 32 + lane) * 4;
    float4 a  = *reinterpret_cast<const float4*>(xr + idx);
    float4 m1 = *reinterpret_cast<const float4*>(fr + idx);
    float4 m2 = *reinterpret_cast<const float4*>(br + idx);
    u[k*4+0]=a.x+m1.x; u[k*4+1]=a.y+m1.y; u[k*4+2]=a.z+m1.z; u[k*4+3]=a.w+m1.w;
    v[k*4+0]=a.x+m2.x; v[k*4+1]=a.y+m2.y; v[k*4+2]=a.z+m2.z; v[k*4+3]=a.w+m2.w;
    #pragma unroll
    for (int c = 0; c < 4; c++) { su += u[k*4+c]; sv += v[k*4+c]; }
  }
  float muU = warp_sum(su) * (1.f / kDM);
  float muV = warp_sum(sv) * (1.f / kDM);
  float qu = 0.f, qv = 0.f;
  #pragma unroll
  for (int c = 0; c < 16; c++) {
    float du = u[c] - muU, dv = v[c] - muV;
    qu += du * du; qv += dv * dv;
  }
  float rsU = rsqrtf(warp_sum(qu) * (1.f / kDM) + 1e-5f);
  float rsV = rsqrtf(warp_sum(qv) * (1.f / kDM) + 1e-5f);

  float* hr  = g_h  + (size_t)row * kDM;
  __half* hh = g_hh + (size_t)row * kDM;
  #pragma unroll
  for (int k = 0; k < 4; k++) {
    int idx = (k * 32 + lane) * 4;
    float4 o;
    #pragma unroll
    for (int c = 0; c < 4; c++) {
      int f = idx + c;
      float a = (u[k*4+c] - muU) * rsU * __ldg(&gf[f]) + __ldg(&bf[f]);
      float bvv = (v[k*4+c] - muV) * rsV * __ldg(&gb[f]) + __ldg(&bb[f]);
      ((float*)&o)[c] = 0.5f * (a + bvv);
    }
    *reinterpret_cast<float4*>(hr + idx) = o;
    uint2 oh = { pack_h2(o.x, o.y), pack_h2(o.z, o.w) };
    *reinterpret_cast<uint2*>(hh + idx) = oh;
  }
}

__global__ void ln_final_k(const float* __restrict__ ff,
    const float* __restrict__ g, const float* __restrict__ bia,
    float* __restrict__ out)
{
  int row  = blockIdx.x * (blockDim.x >> 5) + (threadIdx.x >> 5);
  int lane = threadIdx.x & 31;
  const float* hr = g_h + (size_t)row * kDM;
  const float* fr = ff  + (size_t)row * kDM;

  float u[16];
  float su = 0.f;
  #pragma unroll
  for (int k = 0; k < 4; k++) {
    int idx = (k * 32 + lane) * 4;
    float4 a  = *reinterpret_cast<const float4*>(hr + idx);
    float4 m1 = *reinterpret_cast<const float4*>(fr + idx);
    u[k*4+0]=a.x+m1.x; u[k*4+1]=a.y+m1.y; u[k*4+2]=a.z+m1.z; u[k*4+3]=a.w+m1.w;
    #pragma unroll
    for (int c = 0; c < 4; c++) su += u[k*4+c];
  }
  float mu = warp_sum(su) * (1.f / kDM);
  float q = 0.f;
  #pragma unroll
  for (int c = 0; c < 16; c++) { float d = u[c] - mu; q += d * d; }
  float rs = rsqrtf(warp_sum(q) * (1.f / kDM) + 1e-5f);

  float* orow = out + (size_t)row * kDM;
  #pragma unroll
  for (int k = 0; k < 4; k++) {
    int idx = (k * 32 + lane) * 4;
    float4 o;
    #pragma unroll
    for (int c = 0; c < 4; c++) {
      int f = idx + c;
      ((float*)&o)[c] = (u[k*4+c] - mu) * rs * __ldg(&g[f]) + __ldg(&bia[f]);
    }
    *reinterpret_cast<float4*>(orow + idx) = o;
  }
}

// ---------------------------------------------------------------------------
// Launch
// ---------------------------------------------------------------------------
extern "C" void kernel_launch(void* const* d_in, const int* in_sizes, int n_in,
                              void* d_out, int out_size)
{
  const float* x = (const float*)d_in[0];
  const float* const* Pf = (const float* const*)&d_in[1];
  const float* const* Pb = (const float* const*)&d_in[10];
  const float* ln_f_g  = (const float*)d_in[19];
  const float* ln_f_b  = (const float*)d_in[20];
  const float* ln_b_g  = (const float*)d_in[21];
  const float* ln_b_b  = (const float*)d_in[22];
  const float* ln_ff_g = (const float*)d_in[23];
  const float* ln_ff_b = (const float*)d_in[24];
  const float* ffn_w1  = (const float*)d_in[25];
  const float* ffn_b1  = (const float*)d_in[26];
  const float* ffn_w2  = (const float*)d_in[27];
  const float* ffn_b2  = (const float*)d_in[28];
  float* out = (float*)d_out;

  void *p_xh, *p_xzh, *p_xch, *p_dbch, *p_dth, *p_yh, *p_hh, *p_wh;
  void *p_mf, *p_mb, *p_h;
  cudaGetSymbolAddress(&p_xh,   g_xh);
  cudaGetSymbolAddress(&p_xzh,  g_xzh);
  cudaGetSymbolAddress(&p_xch,  g_xch);
  cudaGetSymbolAddress(&p_dbch, g_dbch);
  cudaGetSymbolAddress(&p_dth,  g_dth);
  cudaGetSymbolAddress(&p_yh,   g_yh);
  cudaGetSymbolAddress(&p_hh,   g_hh);
  cudaGetSymbolAddress(&p_wh,   g_wh);
  cudaGetSymbolAddress(&p_mf,   g_mf);
  cudaGetSymbolAddress(&p_mb,   g_mb);
  cudaGetSymbolAddress(&p_h,    g_h);
  __half* wh = (__half*)p_wh;
  __half* xh = (__half*)p_xh;

  const dim3 blk(128);
  const int rowsY = kT / 128;   // 256

  // One fused fp32->fp16 conversion launch (x + 10 weight tensors)
  {
    CvtJobs jobs;
    const float* srcs[11] = { x, Pf[0], Pb[0], Pf[3], Pb[3], Pf[4], Pb[4],
                              Pf[8], Pb[8], ffn_w1, ffn_w2 };
    __half* dsts[11] = { xh, wh + oInF, wh + oInB, wh + oXpF, wh + oXpB,
                         wh + oDtF, wh + oDtB, wh + oOutF, wh + oOutB,
                         wh + oF1, wh + oF2 };
    size_t ns[11] = { (size_t)kT * kDM, 2048*512, 2048*512, 64*1024, 64*1024,
                      1024*32, 1024*32, 512*1024, 512*1024,
                      2048*512, 512*2048 };
    for (int j = 0; j < 11; j++) {
      jobs.src[j] = (const float4*)srcs[j];
      jobs.dst[j] = (uint2*)dsts[j];
      jobs.n4[j]  = (int)(ns[j] / 4);
    }
    jobs.njobs = 11;
    f2h_all_k<<<dim3(2048, 11), dim3(256)>>>(jobs);
  }

  auto run_block = [&](const float* const* P, float* mout, int dir,
                       const __half* w_in, const __half* w_xp,
                       const __half* w_dt, const __half* w_out) {
    gemm_h<0,1><<<dim3(kDXZ / 64, rowsY), blk>>>(xh, kDM, w_in, nullptr,
                                                 p_xzh, kT, kDXZ, kDM);
    conv_silu_k<<<(kT * kDI) / 256, dim3(256)>>>(P[1], P[2], dir);
    gemm_h<0,1><<<dim3(kDBC / 64, rowsY), blk>>>((const __half*)p_xch, kDI, w_xp,
                                                 nullptr, p_dbch, kT, kDBC, kDI);
    gemm_h<1,1><<<dim3(kDI / 64, rowsY), blk>>>((const __half*)p_dbch, kDBC, w_dt,
                                                P[5], p_dth, kT, kDI, kR);
    scan_k<<<512, dim3(256)>>>(P[6], P[7], dir);
    gemm_h<0,0><<<dim3(kDM / 64, rowsY), blk>>>((const __half*)p_yh, kDI, w_out,
                                                nullptr, mout, kT, kDM, kDI);
  };

  run_block(Pf, (float*)p_mf, +1, wh + oInF, wh + oXpF, wh + oDtF, wh + oOutF);
  run_block(Pb, (float*)p_mb, -1, wh + oInB, wh + oXpB, wh + oDtB, wh + oOutB);

  ln_combine_k<<<kT / 8, dim3(256)>>>(x, ln_f_g, ln_f_b, ln_b_g, ln_b_b);

  gemm_h<2,1><<<dim3(kFF / 64, rowsY), blk>>>((const __half*)p_hh, kDM, wh + oF1,
                                              ffn_b1, p_xzh, kT, kFF, kDM);
  gemm_h<3,0><<<dim3(kDM / 64, rowsY), blk>>>((const __half*)p_xzh, kFF, wh + oF2,
                                              ffn_b2, p_mf, kT, kDM, kFF);

  ln_final_k<<<kT / 8, dim3(256)>>>((const float*)p_mf, ln_ff_g, ln_ff_b, out);
}

// round 14
// speedup vs baseline: 1.8692x; 1.6234x over previous
#include <cuda_runtime.h>
#include <cuda_fp16.h>
#include <cstdint>

// ---------------------------------------------------------------------------
// BiMambaLayer on GB300 — Round 12: R11 + fwd/bwd batched into single
// gridDim.z=2 launches (own scratch per direction). Kernels' inner bodies
// are R11-identical; only pointer selection by blockIdx.z added.
// ---------------------------------------------------------------------------

namespace {
constexpr int kB   = 8;
constexpr int kL   = 4096;
constexpr int kDM  = 512;
constexpr int kDI  = 1024;
constexpr int kDXZ = 2048;
constexpr int kN   = 16;
constexpr int kR   = 32;
constexpr int kDBC = 64;
constexpr int kFF  = 2048;
constexpr int kT   = kB * kL;

constexpr size_t oInF  = 0;
constexpr size_t oInB  = oInF  + 2048 * 512;
constexpr size_t oXpF  = oInB  + 2048 * 512;
constexpr size_t oXpB  = oXpF  + 64 * 1024;
constexpr size_t oDtF  = oXpB  + 64 * 1024;
constexpr size_t oDtB  = oDtF  + 1024 * 32;
constexpr size_t oOutF = oDtB  + 1024 * 32;
constexpr size_t oOutB = oOutF + 512 * 1024;
constexpr size_t oF1   = oOutB + 512 * 1024;
constexpr size_t oF2   = oF1   + 2048 * 512;
constexpr size_t kWH   = oF2   + 512 * 2048;
}

// fp16 activations — forward direction
__device__ __half g_xh   [(size_t)kT * kDM];
__device__ __half g_xzh  [(size_t)kT * kDXZ];   // also ffn hidden
__device__ __half g_xch  [(size_t)kT * kDI];
__device__ __half g_dbch [(size_t)kT * kDBC];
__device__ __half g_dth  [(size_t)kT * kDI];
__device__ __half g_yh   [(size_t)kT * kDI];
// fp16 activations — backward direction
__device__ __half g_xzh2 [(size_t)kT * kDXZ];
__device__ __half g_xch2 [(size_t)kT * kDI];
__device__ __half g_dbch2[(size_t)kT * kDBC];
__device__ __half g_dth2 [(size_t)kT * kDI];
__device__ __half g_yh2  [(size_t)kT * kDI];
__device__ __half g_hh   [(size_t)kT * kDM];
__device__ __half g_wh   [kWH];
// fp32 (output-critical)
__device__ float  g_mf   [(size_t)kT * kDM];    // also ff out
__device__ float  g_mb   [(size_t)kT * kDM];
__device__ float  g_h    [(size_t)kT * kDM];

__device__ __forceinline__ void mma_f16(float* d,
    uint32_t a0, uint32_t a1, uint32_t a2, uint32_t a3,
    uint32_t b0, uint32_t b1)
{
  asm volatile(
    "mma.sync.aligned.m16n8k16.row.col.f32.f16.f16.f32 "
    "{%0,%1,%2,%3}, {%4,%5,%6,%7}, {%8,%9}, {%0,%1,%2,%3};\n"
    : "+f"(d[0]), "+f"(d[1]), "+f"(d[2]), "+f"(d[3])
    : "r"(a0), "r"(a1), "r"(a2), "r"(a3), "r"(b0), "r"(b1));
}
__device__ __forceinline__ void ldsm4(uint32_t* r, uint32_t addr) {
  asm volatile(
    "ldmatrix.sync.aligned.m8n8.x4.shared.b16 {%0,%1,%2,%3}, [%4];"
    : "=r"(r[0]), "=r"(r[1]), "=r"(r[2]), "=r"(r[3]) : "r"(addr));
}
__device__ __forceinline__ void ldsm2(uint32_t& r0, uint32_t& r1, uint32_t addr) {
  asm volatile(
    "ldmatrix.sync.aligned.m8n8.x2.shared.b16 {%0,%1}, [%2];"
    : "=r"(r0), "=r"(r1) : "r"(addr));
}
__device__ __forceinline__ uint32_t pack_h2(float a, float b) {
  __half2 h = __floats2half2_rn(a, b);
  return *reinterpret_cast<uint32_t*>(&h);
}
__device__ __forceinline__ void cpa16(uint32_t s, const void* g) {
  asm volatile("cp.async.cg.shared.global [%0], [%1], 16;" :: "r"(s), "l"(g));
}
__device__ __forceinline__ void cpa_commit() {
  asm volatile("cp.async.commit_group;" ::: "memory");
}
template<int NN>
__device__ __forceinline__ void cpa_wait() {
  asm volatile("cp.async.wait_group %0;" :: "n"(NN) : "memory");
}

// Fused fp32 -> fp16 conversion (one launch, up to 12 segments).
struct CvtJobs {
  const float4* src[12];
  uint2* dst[12];
  int n4[12];
  int njobs;
};
__global__ void f2h_all_k(CvtJobs jobs) {
  int j = blockIdx.y;
  if (j >= jobs.njobs) return;
  const float4* s = jobs.src[j];
  uint2* d = jobs.dst[j];
  int n4 = jobs.n4[j];
  for (int i = blockIdx.x * blockDim.x + threadIdx.x; i < n4;
       i += gridDim.x * blockDim.x) {
    float4 v = s[i];
    uint2 o = { pack_h2(v.x, v.y), pack_h2(v.z, v.w) };
    d[i] = o;
  }
}

// ---------------------------------------------------------------------------
// Batched GEMM: z = blockIdx.z selects (A, W, bias, C) pair.
// C[M,N] = A[M,K](fp16, lda) * W[N,K]^T(fp16) (+ epilogue)
// 3-stage cp.async pipeline, BK=32, one __syncthreads per K-tile.
// EPI: 0 none, 1 softplus(+bias), 2 gelu(+bias), 3 +bias; OUTH: fp16 C.
// 128 threads = 4 warps (2x2), warp tile 64x32. M%128==0, N%64==0, K%32==0.
// ---------------------------------------------------------------------------
template<int EPI, int OUTH>
__global__ void __launch_bounds__(128, 3) gemm_h(
    const __half* __restrict__ A0, const __half* __restrict__ A1, int lda,
    const __half* __restrict__ W0, const __half* __restrict__ W1,
    const float* __restrict__ bias0, const float* __restrict__ bias1,
    void* __restrict__ C0, void* __restrict__ C1, int M, int N, int K)
{
  constexpr int BM = 128, BN = 64, BK = 32, ST2 = 40, STG = 3;
  constexpr int STAGE_H = (BM + BN) * ST2;
  constexpr uint32_t STAGE_B = STAGE_H * 2;
  __shared__ __half Sm[STG * STAGE_H];

  const __half* A    = blockIdx.z ? A1 : A0;
  const __half* W    = blockIdx.z ? W1 : W0;
  const float*  bias = blockIdx.z ? bias1 : bias0;
  void*         Cp   = blockIdx.z ? C1 : C0;

  const int tid  = threadIdx.x;
  const int lane = tid & 31;
  const int wid  = tid >> 5;
  const int wm   = (wid & 1) * 64;
  const int wn   = (wid >> 1) * 32;
  const size_t bm = (size_t)blockIdx.y * BM;
  const int bn   = blockIdx.x * BN;
  const int g4   = lane >> 2;
  const int t4   = lane & 3;
  const int ntiles = K / BK;

  float acc[4][4][4];
  #pragma unroll
  for (int i = 0; i < 4; i++)
    #pragma unroll
    for (int j = 0; j < 4; j++)
      #pragma unroll
      for (int c = 0; c < 4; c++) acc[i][j][c] = 0.f;

  const int ldR = tid >> 2;
  const int ldC = (tid & 3) * 8;

  const __half* aG[4];
  const __half* wG[2];
  uint32_t aDst[4], wDst[2];
  const uint32_t smBase = (uint32_t)__cvta_generic_to_shared(Sm);
  #pragma unroll
  for (int i = 0; i < 4; i++) {
    int r = ldR + 32 * i;
    aG[i]   = &A[(bm + r) * (size_t)lda + ldC];
    aDst[i] = smBase + (uint32_t)((r * ST2 + ldC) * 2);
  }
  #pragma unroll
  for (int i = 0; i < 2; i++) {
    int r = ldR + 32 * i;
    wG[i]   = &W[(size_t)(bn + r) * K + ldC];
    wDst[i] = smBase + (uint32_t)(((BM + r) * ST2 + ldC) * 2);
  }

  auto issue = [&](int stage) {
    const uint32_t so = (uint32_t)stage * STAGE_B;
    #pragma unroll
    for (int i = 0; i < 4; i++) { cpa16(aDst[i] + so, aG[i]); aG[i] += BK; }
    #pragma unroll
    for (int i = 0; i < 2; i++) { cpa16(wDst[i] + so, wG[i]); wG[i] += BK; }
    cpa_commit();
  };

  const int mrow = lane & 7;
  const int mat  = lane >> 3;
  uint32_t aAddr[4], bAddr[4];
  #pragma unroll
  for (int mi = 0; mi < 4; mi++)
    aAddr[mi] = smBase + (uint32_t)(((wm + mi * 16 + (mat & 1) * 8 + mrow) * ST2
                                     + (mat >> 1) * 8) * 2);
  #pragma unroll
  for (int nj = 0; nj < 4; nj++)
    bAddr[nj] = smBase + (uint32_t)(((BM + wn + nj * 8 + mrow) * ST2
                                     + (mat & 1) * 8) * 2);

  if (0 < ntiles) issue(0); else cpa_commit();
  if (1 < ntiles) issue(1); else cpa_commit();

  int stage = 0;
  for (int t = 0; t < ntiles; t++) {
    cpa_wait<1>();
    __syncthreads();

    if (t + 2 < ntiles) issue((stage + 2) % STG); else cpa_commit();

    const uint32_t so = (uint32_t)stage * STAGE_B;
    #pragma unroll
    for (int kk = 0; kk < 2; kk++) {
      uint32_t a[4][4];
      uint32_t b[4][2];
      #pragma unroll
      for (int mi = 0; mi < 4; mi++)
        ldsm4(a[mi], aAddr[mi] + so + (uint32_t)(kk * 32));
      #pragma unroll
      for (int nj = 0; nj < 4; nj++)
        ldsm2(b[nj][0], b[nj][1], bAddr[nj] + so + (uint32_t)(kk * 32));
      #pragma unroll
      for (int mi = 0; mi < 4; mi++)
        #pragma unroll
        for (int nj = 0; nj < 4; nj++)
          mma_f16(acc[mi][nj], a[mi][0], a[mi][1], a[mi][2], a[mi][3],
                  b[nj][0], b[nj][1]);
    }
    stage = (stage + 1 == STG) ? 0 : stage + 1;
  }

  #pragma unroll
  for (int mi = 0; mi < 4; mi++) {
    #pragma unroll
    for (int nj = 0; nj < 4; nj++) {
      size_t r0 = bm + wm + mi * 16 + g4;
      int c0 = bn + wn + nj * 8 + 2 * t4;
      #pragma unroll
      for (int half = 0; half < 2; half++) {
        size_t row = r0 + half * 8;
        float vx = acc[mi][nj][half * 2 + 0];
        float vy = acc[mi][nj][half * 2 + 1];
        if (EPI == 1) {
          vx += __ldg(&bias[c0]);     vy += __ldg(&bias[c0 + 1]);
          vx = fmaxf(vx, 0.f) + log1pf(__expf(-fabsf(vx)));
          vy = fmaxf(vy, 0.f) + log1pf(__expf(-fabsf(vy)));
        } else if (EPI == 2) {
          vx += __ldg(&bias[c0]);     vy += __ldg(&bias[c0 + 1]);
          float tx = tanhf(0.7978845608028654f * (vx + 0.044715f * vx * vx * vx));
          float ty = tanhf(0.7978845608028654f * (vy + 0.044715f * vy * vy * vy));
          vx = 0.5f * vx * (1.f + tx);
          vy = 0.5f * vy * (1.f + ty);
        } else if (EPI == 3) {
          vx += __ldg(&bias[c0]);     vy += __ldg(&bias[c0 + 1]);
        }
        if (OUTH) {
          *reinterpret_cast<uint32_t*>(&((__half*)Cp)[row * (size_t)N + c0]) =
              pack_h2(vx, vy);
        } else {
          float2 v2 = { vx, vy };
          *reinterpret_cast<float2*>(&((float*)Cp)[row * (size_t)N + c0]) = v2;
        }
      }
    }
  }
}

// ---------------------------------------------------------------------------
// Depthwise causal conv (k=4) + bias + silu; blockIdx.z = direction.
// ---------------------------------------------------------------------------
__global__ void conv_silu_k(const float* __restrict__ cwf,
                            const float* __restrict__ cbf,
                            const float* __restrict__ cwb,
                            const float* __restrict__ cbb)
{
  const int z = blockIdx.z;
  const int dir = z ? -1 : 1;
  const float* cw = z ? cwb : cbf == nullptr ? cwf : cwb, *unused = nullptr;
  (void)unused;
  cw = z ? cwb : cwf;
  const float* cb = z ? cbb : cbf;
  const __half* src = z ? g_xzh2 : g_xzh;
  __half* dst = z ? g_xch2 : g_xch;

  int i = blockIdx.x * blockDim.x + threadIdx.x;
  int d = i & (kDI - 1);
  int tok = i >> 10;
  int pos = tok & (kL - 1);
  float acc = __ldg(&cb[d]);
  #pragma unroll
  for (int j = 0; j < 4; j++) {
    int o = (dir > 0) ? (j - 3) : (3 - j);
    int p = pos + o;
    if (p >= 0 && p < kL)
      acc = fmaf(__ldg(&cw[d * 4 + j]),
                 __half2float(src[(size_t)(tok + o) * kDXZ + d]), acc);
  }
  dst[i] = __float2half(acc / (1.f + __expf(-acc)));
}

// ---------------------------------------------------------------------------
// Selective scan; blockIdx.z = direction. Warp = 2 channels (16 lanes each).
// ---------------------------------------------------------------------------
__global__ void scan_k(const float* __restrict__ A_log_f,
                       const float* __restrict__ Dp_f,
                       const float* __restrict__ A_log_b,
                       const float* __restrict__ Dp_b)
{
  const int z = blockIdx.z;
  const int dir = z ? -1 : 1;
  const float* A_log = z ? A_log_b : A_log_f;
  const float* Dp    = z ? Dp_b    : Dp_f;
  const __half* dth  = z ? g_dth2  : g_dth;
  const __half* xch  = z ? g_xch2  : g_xch;
  const __half* dbch = z ? g_dbch2 : g_dbch;
  const __half* xzh  = z ? g_xzh2  : g_xzh;
  __half* yh         = z ? g_yh2   : g_yh;

  int gw   = (blockIdx.x * blockDim.x + threadIdx.x) >> 5;
  int lane = threadIdx.x & 31;
  int half = lane >> 4;
  int n    = lane & 15;
  int ch   = gw * 2 + half;
  int b    = ch >> 10;
  int d    = ch & (kDI - 1);

  float A  = -__expf(__ldg(&A_log[d * kN + n]));
  float Dv = __ldg(&Dp[d]);
  float h  = 0.f;
  const size_t tokbase = (size_t)b * kL;

  for (int u = 0; u < kL; ++u) {
    int pos = (dir > 0) ? u : (kL - 1 - u);
    size_t tok = tokbase + pos;
    float dtv = __half2float(dth [tok * kDI  + d]);
    float xv  = __half2float(xch [tok * kDI  + d]);
    float Bv  = __half2float(dbch[tok * kDBC + kR + n]);
    float Cv  = __half2float(dbch[tok * kDBC + kR + kN + n]);
    float a   = __expf(dtv * A);
    h = fmaf(a, h, dtv * xv * Bv);
    float p = h * Cv;
    p += __shfl_xor_sync(0xffffffffu, p, 1);
    p += __shfl_xor_sync(0xffffffffu, p, 2);
    p += __shfl_xor_sync(0xffffffffu, p, 4);
    p += __shfl_xor_sync(0xffffffffu, p, 8);
    if (n == 0) {
      float zv = __half2float(xzh[tok * kDXZ + kDI + d]);
      float sz = zv / (1.f + __expf(-zv));
      yh[tok * kDI + d] = __float2half((p + xv * Dv) * sz);
    }
  }
}

// ---------------------------------------------------------------------------
// LayerNorms
// ---------------------------------------------------------------------------
__device__ __forceinline__ float warp_sum(float v) {
  v += __shfl_xor_sync(0xffffffffu, v, 16);
  v += __shfl_xor_sync(0xffffffffu, v, 8);
  v += __shfl_xor_sync(0xffffffffu, v, 4);
  v += __shfl_xor_sync(0xffffffffu, v, 2);
  v += __shfl_xor_sync(0xffffffffu, v, 1);
  return v;
}

__global__ void ln_combine_k(const float* __restrict__ x,
    const float* __restrict__ gf, const float* __restrict__ bf,
    const float* __restrict__ gb, const float* __restrict__ bb)
{
  int row  = blockIdx.x * (blockDim.x >> 5) + (threadIdx.x >> 5);
  int lane = threadIdx.x & 31;
  const float* xr = x    + (size_t)row * kDM;
  const float* fr = g_mf + (size_t)row * kDM;
  const float* br = g_mb + (size_t)row * kDM;

  float u[16], v[16];
  float su = 0.f, sv = 0.f;
  #pragma unroll
  for (int k = 0; k < 4; k++) {
    int idx = (k * 32 + lane) * 4;
    float4 a  = *reinterpret_cast<const float4*>(xr + idx);
    float4 m1 = *reinterpret_cast<const float4*>(fr + idx);
    float4 m2 = *reinterpret_cast<const float4*>(br + idx);
    u[k*4+0]=a.x+m1.x; u[k*4+1]=a.y+m1.y; u[k*4+2]=a.z+m1.z; u[k*4+3]=a.w+m1.w;
    v[k*4+0]=a.x+m2.x; v[k*4+1]=a.y+m2.y; v[k*4+2]=a.z+m2.z; v[k*4+3]=a.w+m2.w;
    #pragma unroll
    for (int c = 0; c < 4; c++) { su += u[k*4+c]; sv += v[k*4+c]; }
  }
  float muU = warp_sum(su) * (1.f / kDM);
  float muV = warp_sum(sv) * (1.f / kDM);
  float qu = 0.f, qv = 0.f;
  #pragma unroll
  for (int c = 0; c < 16; c++) {
    float du = u[c] - muU, dv = v[c] - muV;
    qu += du * du; qv += dv * dv;
  }
  float rsU = rsqrtf(warp_sum(qu) * (1.f / kDM) + 1e-5f);
  float rsV = rsqrtf(warp_sum(qv) * (1.f / kDM) + 1e-5f);

  float* hr  = g_h  + (size_t)row * kDM;
  __half* hh = g_hh + (size_t)row * kDM;
  #pragma unroll
  for (int k = 0; k < 4; k++) {
    int idx = (k * 32 + lane) * 4;
    float4 o;
    #pragma unroll
    for (int c = 0; c < 4; c++) {
      int f = idx + c;
      float a = (u[k*4+c] - muU) * rsU * __ldg(&gf[f]) + __ldg(&bf[f]);
      float bvv = (v[k*4+c] - muV) * rsV * __ldg(&gb[f]) + __ldg(&bb[f]);
      ((float*)&o)[c] = 0.5f * (a + bvv);
    }
    *reinterpret_cast<float4*>(hr + idx) = o;
    uint2 oh = { pack_h2(o.x, o.y), pack_h2(o.z, o.w) };
    *reinterpret_cast<uint2*>(hh + idx) = oh;
  }
}

__global__ void ln_final_k(const float* __restrict__ ff,
    const float* __restrict__ g, const float* __restrict__ bia,
    float* __restrict__ out)
{
  int row  = blockIdx.x * (blockDim.x >> 5) + (threadIdx.x >> 5);
  int lane = threadIdx.x & 31;
  const float* hr = g_h + (size_t)row * kDM;
  const float* fr = ff  + (size_t)row * kDM;

  float u[16];
  float su = 0.f;
  #pragma unroll
  for (int k = 0; k < 4; k++) {
    int idx = (k * 32 + lane) * 4;
    float4 a  = *reinterpret_cast<const float4*>(hr + idx);
    float4 m1 = *reinterpret_cast<const float4*>(fr + idx);
    u[k*4+0]=a.x+m1.x; u[k*4+1]=a.y+m1.y; u[k*4+2]=a.z+m1.z; u[k*4+3]=a.w+m1.w;
    #pragma unroll
    for (int c = 0; c < 4; c++) su += u[k*4+c];
  }
  float mu = warp_sum(su) * (1.f / kDM);
  float q = 0.f;
  #pragma unroll
  for (int c = 0; c < 16; c++) { float d = u[c] - mu; q += d * d; }
  float rs = rsqrtf(warp_sum(q) * (1.f / kDM) + 1e-5f);

  float* orow = out + (size_t)row * kDM;
  #pragma unroll
  for (int k = 0; k < 4; k++) {
    int idx = (k * 32 + lane) * 4;
    float4 o;
    #pragma unroll
    for (int c = 0; c < 4; c++) {
      int f = idx + c;
      ((float*)&o)[c] = (u[k*4+c] - mu) * rs * __ldg(&g[f]) + __ldg(&bia[f]);
    }
    *reinterpret_cast<float4*>(orow + idx) = o;
  }
}

// ---------------------------------------------------------------------------
// Launch
// ---------------------------------------------------------------------------
extern "C" void kernel_launch(void* const* d_in, const int* in_sizes, int n_in,
                              void* d_out, int out_size)
{
  const float* x = (const float*)d_in[0];
  const float* const* Pf = (const float* const*)&d_in[1];
  const float* const* Pb = (const float* const*)&d_in[10];
  const float* ln_f_g  = (const float*)d_in[19];
  const float* ln_f_b  = (const float*)d_in[20];
  const float* ln_b_g  = (const float*)d_in[21];
  const float* ln_b_b  = (const float*)d_in[22];
  const float* ln_ff_g = (const float*)d_in[23];
  const float* ln_ff_b = (const float*)d_in[24];
  const float* ffn_w1  = (const float*)d_in[25];
  const float* ffn_b1  = (const float*)d_in[26];
  const float* ffn_w2  = (const float*)d_in[27];
  const float* ffn_b2  = (const float*)d_in[28];
  float* out = (float*)d_out;

  void *p_xh, *p_xzh, *p_xch, *p_dbch, *p_dth, *p_yh;
  void *p_xzh2, *p_xch2, *p_dbch2, *p_dth2, *p_yh2;
  void *p_hh, *p_wh, *p_mf, *p_mb, *p_h;
  cudaGetSymbolAddress(&p_xh,    g_xh);
  cudaGetSymbolAddress(&p_xzh,   g_xzh);
  cudaGetSymbolAddress(&p_xch,   g_xch);
  cudaGetSymbolAddress(&p_dbch,  g_dbch);
  cudaGetSymbolAddress(&p_dth,   g_dth);
  cudaGetSymbolAddress(&p_yh,    g_yh);
  cudaGetSymbolAddress(&p_xzh2,  g_xzh2);
  cudaGetSymbolAddress(&p_xch2,  g_xch2);
  cudaGetSymbolAddress(&p_dbch2, g_dbch2);
  cudaGetSymbolAddress(&p_dth2,  g_dth2);
  cudaGetSymbolAddress(&p_yh2,   g_yh2);
  cudaGetSymbolAddress(&p_hh,    g_hh);
  cudaGetSymbolAddress(&p_wh,    g_wh);
  cudaGetSymbolAddress(&p_mf,    g_mf);
  cudaGetSymbolAddress(&p_mb,    g_mb);
  cudaGetSymbolAddress(&p_h,     g_h);
  __half* wh = (__half*)p_wh;
  __half* xh = (__half*)p_xh;

  const dim3 blk(128);
  const int rowsY = kT / 128;   // 256

  // One fused fp32->fp16 conversion launch (x + 10 weight tensors)
  {
    CvtJobs jobs;
    const float* srcs[11] = { x, Pf[0], Pb[0], Pf[3], Pb[3], Pf[4], Pb[4],
                              Pf[8], Pb[8], ffn_w1, ffn_w2 };
    __half* dsts[11] = { xh, wh + oInF, wh + oInB, wh + oXpF, wh + oXpB,
                         wh + oDtF, wh + oDtB, wh + oOutF, wh + oOutB,
                         wh + oF1, wh + oF2 };
    size_t ns[11] = { (size_t)kT * kDM, 2048*512, 2048*512, 64*1024, 64*1024,
                      1024*32, 1024*32, 512*1024, 512*1024,
                      2048*512, 512*2048 };
    for (int j = 0; j < 11; j++) {
      jobs.src[j] = (const float4*)srcs[j];
      jobs.dst[j] = (uint2*)dsts[j];
      jobs.n4[j]  = (int)(ns[j] / 4);
    }
    jobs.njobs = 11;
    f2h_all_k<<<dim3(2048, 11), dim3(256)>>>(jobs);
  }

  // ---- Batched fwd+bwd mamba pipeline (gridDim.z = 2) ----
  // 1) in_proj: xz = x @ in_w^T
  gemm_h<0,1><<<dim3(kDXZ / 64, rowsY, 2), blk>>>(
      xh, xh, kDM, wh + oInF, wh + oInB, nullptr, nullptr,
      p_xzh, p_xzh2, kT, kDXZ, kDM);
  // 2) conv + silu
  conv_silu_k<<<dim3((kT * kDI) / 256, 1, 2), dim3(256)>>>(
      Pf[1], Pf[2], Pb[1], Pb[2]);
  // 3) xproj: dbc = xc @ xproj^T
  gemm_h<0,1><<<dim3(kDBC / 64, rowsY, 2), blk>>>(
      (const __half*)p_xch, (const __half*)p_xch2, kDI,
      wh + oXpF, wh + oXpB, nullptr, nullptr,
      p_dbch, p_dbch2, kT, kDBC, kDI);
  // 4) dt = softplus(dbc[:, :32] @ dt_w^T + dt_b)
  gemm_h<1,1><<<dim3(kDI / 64, rowsY, 2), blk>>>(
      (const __half*)p_dbch, (const __half*)p_dbch2, kDBC,
      wh + oDtF, wh + oDtB, Pf[5], Pb[5],
      p_dth, p_dth2, kT, kDI, kR);
  // 5) scan
  scan_k<<<dim3(512, 1, 2), dim3(256)>>>(Pf[6], Pf[7], Pb[6], Pb[7]);
  // 6) out_proj: m = y @ out_w^T  (fp32 out)
  gemm_h<0,0><<<dim3(kDM / 64, rowsY, 2), blk>>>(
      (const __half*)p_yh, (const __half*)p_yh2, kDI,
      wh + oOutF, wh + oOutB, nullptr, nullptr,
      p_mf, p_mb, kT, kDM, kDI);

  // ---- Combine + FFN + final LN ----
  ln_combine_k<<<kT / 8, dim3(256)>>>(x, ln_f_g, ln_f_b, ln_b_g, ln_b_b);

  gemm_h<2,1><<<dim3(kFF / 64, rowsY, 1), blk>>>(
      (const __half*)p_hh, (const __half*)p_hh, kDM,
      wh + oF1, wh + oF1, ffn_b1, ffn_b1,
      p_xzh, p_xzh, kT, kFF, kDM);
  gemm_h<3,0><<<dim3(kDM / 64, rowsY, 1), blk>>>(
      (const __half*)p_xzh, (const __half*)p_xzh, kFF,
      wh + oF2, wh + oF2, ffn_b2, ffn_b2,
      p_mf, p_mf, kT, kDM, kFF);

  ln_final_k<<<kT / 8, dim3(256)>>>((const float*)p_mf, ln_ff_g, ln_ff_b, out);
}